// round 3
// baseline (speedup 1.0000x reference)
#include <cuda_runtime.h>
#include <cstdint>

// Problem constants
constexpr int Bb   = 2;
constexpr int T    = 2048;
constexpr int Cc   = 1024;
constexpr int H    = 16;
constexpr int D    = 64;
constexpr int HD   = H * D;          // 1024
constexpr int QKV3 = 3 * HD;         // 3072
constexpr int M_ROWS = Bb * T;       // 4096

// Scratch (no cudaMalloc allowed)
__device__ float g_qkv[(size_t)M_ROWS * QKV3];   // (B*T, 3072)
__device__ float g_attn[(size_t)M_ROWS * HD];    // (B*T, 1024)

// ---------------------------------------------------------------------------
// tf32 helpers
// ---------------------------------------------------------------------------
__device__ __forceinline__ uint32_t f2tf32(float x) {
    uint32_t r;
    asm("cvt.rna.tf32.f32 %0, %1;" : "=r"(r) : "f"(x));
    return r;
}

// D += A(16x8,row) * B(8x8,col)  tf32 inputs, f32 accum
__device__ __forceinline__ void mma8(float& d0, float& d1, float& d2, float& d3,
                                     uint32_t a0, uint32_t a1, uint32_t a2, uint32_t a3,
                                     uint32_t b0, uint32_t b1) {
    asm volatile(
        "mma.sync.aligned.m16n8k8.row.col.f32.tf32.tf32.f32 "
        "{%0,%1,%2,%3}, {%4,%5,%6,%7}, {%8,%9}, {%0,%1,%2,%3};\n"
        : "+f"(d0), "+f"(d1), "+f"(d2), "+f"(d3)
        : "r"(a0), "r"(a1), "r"(a2), "r"(a3), "r"(b0), "r"(b1));
}

// ---------------------------------------------------------------------------
// tf32 GEMM: C = A @ Bm^T + bias.  A: MxK row-major, Bm: NxK row-major.
// 128x128 tile, BK=16, 256 threads (8 warps, 2x4 over MxN).
// Register-prefetch double buffering: next tile's LDGs issued right after the
// store-phase sync, consumed one full compute phase later.
// smem stride GS=20 words -> all frag LDS conflict-free.
// ---------------------------------------------------------------------------
constexpr int GS = 20;

__global__ __launch_bounds__(256) void gemm_tf32(
    int M, int N, int K,
    const float* __restrict__ A,
    const float* __restrict__ Bm,
    const float* __restrict__ bias,
    float* __restrict__ C)
{
    __shared__ uint32_t As[128 * GS];
    __shared__ uint32_t Bs[128 * GS];

    const int tid  = threadIdx.x;
    const int lane = tid & 31;
    const int wid  = tid >> 5;
    const int wm   = (wid & 1) * 64;
    const int wn   = (wid >> 1) * 32;
    const int m0   = blockIdx.y * 128;
    const int n0   = blockIdx.x * 128;
    const int lr   = lane >> 2;
    const int lc   = lane & 3;

    float acc[4][4][4] = {};

    const int row = tid >> 2;            // 0..63
    const int kc  = (tid & 3) << 2;      // 0,4,8,12
    const float* Aptr = &A[(size_t)(m0 + row) * K + kc];
    const float* Bptr = &Bm[(size_t)(n0 + row) * K + kc];
    const size_t rs64 = (size_t)64 * K;

    // Prologue: prefetch tile 0 into registers
    float4 pa0 = *(const float4*)(Aptr);
    float4 pa1 = *(const float4*)(Aptr + rs64);
    float4 pb0 = *(const float4*)(Bptr);
    float4 pb1 = *(const float4*)(Bptr + rs64);

    const int nk = K >> 4;
    for (int ki = 0; ki < nk; ki++) {
        // Store prefetched tile (convert to tf32), STS.128
        {
            uint4 w;
            w.x = f2tf32(pa0.x); w.y = f2tf32(pa0.y); w.z = f2tf32(pa0.z); w.w = f2tf32(pa0.w);
            *(uint4*)&As[row * GS + kc] = w;
            w.x = f2tf32(pa1.x); w.y = f2tf32(pa1.y); w.z = f2tf32(pa1.z); w.w = f2tf32(pa1.w);
            *(uint4*)&As[(row + 64) * GS + kc] = w;
            w.x = f2tf32(pb0.x); w.y = f2tf32(pb0.y); w.z = f2tf32(pb0.z); w.w = f2tf32(pb0.w);
            *(uint4*)&Bs[row * GS + kc] = w;
            w.x = f2tf32(pb1.x); w.y = f2tf32(pb1.y); w.z = f2tf32(pb1.z); w.w = f2tf32(pb1.w);
            *(uint4*)&Bs[(row + 64) * GS + kc] = w;
        }
        __syncthreads();

        // Prefetch next tile (latency hidden by compute below)
        if (ki + 1 < nk) {
            const float* a2 = Aptr + (ki + 1) * 16;
            const float* b2 = Bptr + (ki + 1) * 16;
            pa0 = *(const float4*)(a2);
            pa1 = *(const float4*)(a2 + rs64);
            pb0 = *(const float4*)(b2);
            pb1 = *(const float4*)(b2 + rs64);
        }

#pragma unroll
        for (int kk = 0; kk < 16; kk += 8) {
            uint32_t a[4][4], b[4][2];
#pragma unroll
            for (int i = 0; i < 4; i++) {
                const int r = wm + i * 16 + lr;
                a[i][0] = As[r * GS + kk + lc];
                a[i][1] = As[(r + 8) * GS + kk + lc];
                a[i][2] = As[r * GS + kk + lc + 4];
                a[i][3] = As[(r + 8) * GS + kk + lc + 4];
            }
#pragma unroll
            for (int j = 0; j < 4; j++) {
                const int n = wn + j * 8 + lr;
                b[j][0] = Bs[n * GS + kk + lc];
                b[j][1] = Bs[n * GS + kk + lc + 4];
            }
#pragma unroll
            for (int i = 0; i < 4; i++)
#pragma unroll
                for (int j = 0; j < 4; j++)
                    mma8(acc[i][j][0], acc[i][j][1], acc[i][j][2], acc[i][j][3],
                         a[i][0], a[i][1], a[i][2], a[i][3], b[j][0], b[j][1]);
        }
        __syncthreads();
    }

#pragma unroll
    for (int i = 0; i < 4; i++) {
        const int r = m0 + wm + i * 16 + lr;
#pragma unroll
        for (int j = 0; j < 4; j++) {
            const int c = n0 + wn + j * 8 + 2 * lc;
            const float2 bi = *(const float2*)&bias[c];
            float2 v0 = { acc[i][j][0] + bi.x, acc[i][j][1] + bi.y };
            *(float2*)&C[(size_t)r * N + c] = v0;
            float2 v1 = { acc[i][j][2] + bi.x, acc[i][j][3] + bi.y };
            *(float2*)&C[(size_t)(r + 8) * N + c] = v1;
        }
    }
}

// ---------------------------------------------------------------------------
// Flash attention (tf32 mma) with sink.
// Br=128 q rows per CTA (256 threads, 8 warps x 16 rows), Bc=64.
// Register-prefetch double buffering for K/V tiles; warps skip fully-masked
// tiles. Smem strides AS=68, VS=72 -> conflict-free frag LDS.
// ---------------------------------------------------------------------------
constexpr int AS = 68;
constexpr int VS = 72;
constexpr int ATTN_SMEM =
    (128 * AS + 64 * AS + 64 * VS + 128 * AS) * (int)sizeof(uint32_t); // 105472 B

__global__ __launch_bounds__(256) void attn_tf32(
    const float* __restrict__ qkv,
    const float* __restrict__ sink_logit,
    float* __restrict__ attn_out)
{
    extern __shared__ uint32_t sm[];
    uint32_t* Qs = sm;                   // [128][AS] tf32 (scaled)
    uint32_t* Ks = Qs + 128 * AS;        // [64][AS]
    uint32_t* Vs = Ks + 64 * AS;         // [64][VS]
    uint32_t* Ps = Vs + 64 * VS;         // [128][AS]

    const int qt  = blockIdx.x;
    const int h   = blockIdx.y;
    const int b   = blockIdx.z;
    const int tid = threadIdx.x;
    const int lane = tid & 31;
    const int wid  = tid >> 5;
    const int t0   = qt * 128;
    const int mb   = wid * 16;
    const int lr   = lane >> 2;
    const int lc   = lane & 3;
    const float SC = 0.125f;

    // Load Q (scaled, tf32) : 128 rows x 16 float4 = 2048 slots / 256 threads
    for (int i = tid; i < 128 * 16; i += 256) {
        const int r  = i >> 4;
        const int c4 = (i & 15) << 2;
        float4 v = *(const float4*)&qkv[(size_t)(b * T + t0 + r) * QKV3 + h * D + c4];
        uint4 w = { f2tf32(v.x * SC), f2tf32(v.y * SC), f2tf32(v.z * SC), f2tf32(v.w * SC) };
        *(uint4*)&Qs[r * AS + c4] = w;
    }

    const float sink = sink_logit[h];
    float m0v = sink, m1v = sink, l0 = 1.f, l1 = 1.f;
    float o[8][4] = {};

    const int nkt = 2 * qt + 2;   // kv tiles of 64 covering rows t0..t0+127
    float4 pk[4], pv[4];

    // Prologue prefetch kt=0
#pragma unroll
    for (int p = 0; p < 4; p++) {
        const int s  = tid + p * 256;
        const int r  = s >> 4;
        const int c4 = (s & 15) << 2;
        const size_t base = (size_t)(b * T + r) * QKV3 + h * D;
        pk[p] = *(const float4*)&qkv[base + HD + c4];
        pv[p] = *(const float4*)&qkv[base + 2 * HD + c4];
    }

    for (int kt = 0; kt < nkt; kt++) {
        const int kb = kt * 64;
        // Store prefetched K/V (convert to tf32)
#pragma unroll
        for (int p = 0; p < 4; p++) {
            const int s  = tid + p * 256;
            const int r  = s >> 4;
            const int c4 = (s & 15) << 2;
            uint4 wk = { f2tf32(pk[p].x), f2tf32(pk[p].y), f2tf32(pk[p].z), f2tf32(pk[p].w) };
            *(uint4*)&Ks[r * AS + c4] = wk;
            uint4 wv = { f2tf32(pv[p].x), f2tf32(pv[p].y), f2tf32(pv[p].z), f2tf32(pv[p].w) };
            *(uint4*)&Vs[r * VS + c4] = wv;
        }
        __syncthreads();

        // Prefetch next K/V tile
        if (kt + 1 < nkt) {
#pragma unroll
            for (int p = 0; p < 4; p++) {
                const int s  = tid + p * 256;
                const int r  = s >> 4;
                const int c4 = (s & 15) << 2;
                const size_t base = (size_t)(b * T + (kt + 1) * 64 + r) * QKV3 + h * D;
                pk[p] = *(const float4*)&qkv[base + HD + c4];
                pv[p] = *(const float4*)&qkv[base + 2 * HD + c4];
            }
        }

        // Warp-level causal skip: this warp's q rows are [t0+mb, t0+mb+15]
        if (kb <= t0 + mb + 15) {
            // S = Q K^T
            float s[8][4] = {};
#pragma unroll
            for (int kk = 0; kk < 64; kk += 8) {
                const uint32_t a0 = Qs[(mb + lr) * AS + kk + lc];
                const uint32_t a1 = Qs[(mb + 8 + lr) * AS + kk + lc];
                const uint32_t a2 = Qs[(mb + lr) * AS + kk + lc + 4];
                const uint32_t a3 = Qs[(mb + 8 + lr) * AS + kk + lc + 4];
#pragma unroll
                for (int j = 0; j < 8; j++) {
                    const uint32_t b0 = Ks[(j * 8 + lr) * AS + kk + lc];
                    const uint32_t b1 = Ks[(j * 8 + lr) * AS + kk + lc + 4];
                    mma8(s[j][0], s[j][1], s[j][2], s[j][3], a0, a1, a2, a3, b0, b1);
                }
            }

            if (kb + 63 > t0 + mb) {   // tile touches the causal boundary
                const int qr0 = t0 + mb + lr, qr1 = qr0 + 8;
#pragma unroll
                for (int j = 0; j < 8; j++) {
                    const int c = kb + j * 8 + 2 * lc;
                    if (c     > qr0) s[j][0] = -1e30f;
                    if (c + 1 > qr0) s[j][1] = -1e30f;
                    if (c     > qr1) s[j][2] = -1e30f;
                    if (c + 1 > qr1) s[j][3] = -1e30f;
                }
            }

            // Online softmax (rows lr -> regs 0,1 ; lr+8 -> regs 2,3)
            float rmax0 = -1e30f, rmax1 = -1e30f;
#pragma unroll
            for (int j = 0; j < 8; j++) {
                rmax0 = fmaxf(rmax0, fmaxf(s[j][0], s[j][1]));
                rmax1 = fmaxf(rmax1, fmaxf(s[j][2], s[j][3]));
            }
            rmax0 = fmaxf(rmax0, __shfl_xor_sync(~0u, rmax0, 1));
            rmax0 = fmaxf(rmax0, __shfl_xor_sync(~0u, rmax0, 2));
            rmax1 = fmaxf(rmax1, __shfl_xor_sync(~0u, rmax1, 1));
            rmax1 = fmaxf(rmax1, __shfl_xor_sync(~0u, rmax1, 2));

            const float mn0 = fmaxf(m0v, rmax0), mn1 = fmaxf(m1v, rmax1);
            const float sc0 = __expf(m0v - mn0), sc1 = __expf(m1v - mn1);
            float rs0 = 0.f, rs1 = 0.f;
#pragma unroll
            for (int j = 0; j < 8; j++) {
                s[j][0] = __expf(s[j][0] - mn0);
                s[j][1] = __expf(s[j][1] - mn0);
                s[j][2] = __expf(s[j][2] - mn1);
                s[j][3] = __expf(s[j][3] - mn1);
                rs0 += s[j][0] + s[j][1];
                rs1 += s[j][2] + s[j][3];
            }
            rs0 += __shfl_xor_sync(~0u, rs0, 1); rs0 += __shfl_xor_sync(~0u, rs0, 2);
            rs1 += __shfl_xor_sync(~0u, rs1, 1); rs1 += __shfl_xor_sync(~0u, rs1, 2);
            l0 = l0 * sc0 + rs0;  l1 = l1 * sc1 + rs1;
            m0v = mn0;  m1v = mn1;

#pragma unroll
            for (int j = 0; j < 8; j++) {
                o[j][0] *= sc0; o[j][1] *= sc0;
                o[j][2] *= sc1; o[j][3] *= sc1;
                const int c = j * 8 + 2 * lc;
                uint2 w0 = { f2tf32(s[j][0]), f2tf32(s[j][1]) };
                *(uint2*)&Ps[(mb + lr) * AS + c] = w0;
                uint2 w1 = { f2tf32(s[j][2]), f2tf32(s[j][3]) };
                *(uint2*)&Ps[(mb + 8 + lr) * AS + c] = w1;
            }
            __syncwarp();   // P rows are warp-private

            // O += P @ V
#pragma unroll
            for (int cc = 0; cc < 64; cc += 8) {
                const uint32_t a0 = Ps[(mb + lr) * AS + cc + lc];
                const uint32_t a1 = Ps[(mb + 8 + lr) * AS + cc + lc];
                const uint32_t a2 = Ps[(mb + lr) * AS + cc + lc + 4];
                const uint32_t a3 = Ps[(mb + 8 + lr) * AS + cc + lc + 4];
#pragma unroll
                for (int j = 0; j < 8; j++) {
                    const uint32_t b0 = Vs[(cc + lc) * VS + j * 8 + lr];
                    const uint32_t b1 = Vs[(cc + lc + 4) * VS + j * 8 + lr];
                    mma8(o[j][0], o[j][1], o[j][2], o[j][3], a0, a1, a2, a3, b0, b1);
                }
            }
        }
        __syncthreads();
    }

    // Epilogue
    const float inv0 = 1.f / l0, inv1 = 1.f / l1;
#pragma unroll
    for (int j = 0; j < 8; j++) {
        const int c = h * D + j * 8 + 2 * lc;
        float2 v0 = { o[j][0] * inv0, o[j][1] * inv0 };
        *(float2*)&attn_out[(size_t)(b * T + t0 + mb + lr) * HD + c] = v0;
        float2 v1 = { o[j][2] * inv1, o[j][3] * inv1 };
        *(float2*)&attn_out[(size_t)(b * T + t0 + mb + 8 + lr) * HD + c] = v1;
    }
}

// ---------------------------------------------------------------------------
// Launch
// ---------------------------------------------------------------------------
extern "C" void kernel_launch(void* const* d_in, const int* in_sizes, int n_in,
                              void* d_out, int out_size)
{
    const float* x      = (const float*)d_in[0];
    const float* W_qkv  = (const float*)d_in[1];
    const float* b_qkv  = (const float*)d_in[2];
    const float* W_proj = (const float*)d_in[3];
    const float* b_proj = (const float*)d_in[4];
    const float* sink   = (const float*)d_in[5];
    float* out = (float*)d_out;

    float* qkvbuf  = nullptr;
    float* attnbuf = nullptr;
    cudaGetSymbolAddress((void**)&qkvbuf, g_qkv);
    cudaGetSymbolAddress((void**)&attnbuf, g_attn);

    cudaFuncSetAttribute(attn_tf32,
                         cudaFuncAttributeMaxDynamicSharedMemorySize, ATTN_SMEM);

    // 1) QKV GEMM: (4096,1024) @ (3072,1024)^T -> (4096,3072)
    gemm_tf32<<<dim3(QKV3 / 128, M_ROWS / 128), 256>>>(
        M_ROWS, QKV3, Cc, x, W_qkv, b_qkv, qkvbuf);

    // 2) Flash attention with sink -> (4096,1024)
    attn_tf32<<<dim3(T / 128, H, Bb), 256, ATTN_SMEM>>>(qkvbuf, sink, attnbuf);

    // 3) Proj GEMM: (4096,1024) @ (1024,1024)^T + bias -> d_out
    gemm_tf32<<<dim3(HD / 128, M_ROWS / 128), 256>>>(
        M_ROWS, HD, HD, attnbuf, W_proj, b_proj, out);
}

// round 4
// speedup vs baseline: 1.0908x; 1.0908x over previous
#include <cuda_runtime.h>
#include <cstdint>

// Problem constants
constexpr int Bb   = 2;
constexpr int T    = 2048;
constexpr int Cc   = 1024;
constexpr int H    = 16;
constexpr int D    = 64;
constexpr int HD   = H * D;          // 1024
constexpr int QKV3 = 3 * HD;         // 3072
constexpr int M_ROWS = Bb * T;       // 4096

// Scratch (no cudaMalloc allowed)
__device__ float g_qkv[(size_t)M_ROWS * QKV3];   // (B*T, 3072)
__device__ float g_attn[(size_t)M_ROWS * HD];    // (B*T, 1024)

// ---------------------------------------------------------------------------
// tf32 helpers
// ---------------------------------------------------------------------------
__device__ __forceinline__ uint32_t f2tf32(float x) {
    uint32_t r;
    asm("cvt.rna.tf32.f32 %0, %1;" : "=r"(r) : "f"(x));
    return r;
}

// D += A(16x8,row) * B(8x8,col)  tf32 inputs, f32 accum
__device__ __forceinline__ void mma8(float& d0, float& d1, float& d2, float& d3,
                                     uint32_t a0, uint32_t a1, uint32_t a2, uint32_t a3,
                                     uint32_t b0, uint32_t b1) {
    asm volatile(
        "mma.sync.aligned.m16n8k8.row.col.f32.tf32.tf32.f32 "
        "{%0,%1,%2,%3}, {%4,%5,%6,%7}, {%8,%9}, {%0,%1,%2,%3};\n"
        : "+f"(d0), "+f"(d1), "+f"(d2), "+f"(d3)
        : "r"(a0), "r"(a1), "r"(a2), "r"(a3), "r"(b0), "r"(b1));
}

// ---------------------------------------------------------------------------
// tf32 GEMM, double-buffered smem: C = A @ Bm^T + bias.
// A: MxK row-major, Bm: NxK row-major. 128x128 tile, BK=16, 256 threads.
// One __syncthreads per k-step; store into stage s^1 while computing stage s.
// smem stride GS=20 words -> all frag LDS conflict-free.
// ---------------------------------------------------------------------------
constexpr int GS = 20;
constexpr int GEMM_STAGE = 128 * GS;                       // words per matrix per stage
constexpr int GEMM_SMEM  = 2 * 2 * GEMM_STAGE * 4;         // 81920 B

__global__ __launch_bounds__(256) void gemm_tf32(
    int M, int N, int K,
    const float* __restrict__ A,
    const float* __restrict__ Bm,
    const float* __restrict__ bias,
    float* __restrict__ C)
{
    extern __shared__ uint32_t dsm[];
    uint32_t* As = dsm;                    // [2][128*GS]
    uint32_t* Bs = dsm + 2 * GEMM_STAGE;   // [2][128*GS]

    const int tid  = threadIdx.x;
    const int lane = tid & 31;
    const int wid  = tid >> 5;
    const int wm   = (wid & 1) * 64;
    const int wn   = (wid >> 1) * 32;
    const int m0   = blockIdx.y * 128;
    const int n0   = blockIdx.x * 128;
    const int lr   = lane >> 2;
    const int lc   = lane & 3;

    float acc[4][4][4] = {};

    const int row = tid >> 2;            // 0..63
    const int kc  = (tid & 3) << 2;      // 0,4,8,12
    const float* Aptr = &A[(size_t)(m0 + row) * K + kc];
    const float* Bptr = &Bm[(size_t)(n0 + row) * K + kc];
    const size_t rs64 = (size_t)64 * K;

    // Prologue: load tile 0, store into stage 0
    float4 pa0 = *(const float4*)(Aptr);
    float4 pa1 = *(const float4*)(Aptr + rs64);
    float4 pb0 = *(const float4*)(Bptr);
    float4 pb1 = *(const float4*)(Bptr + rs64);
    {
        uint4 w;
        w.x = f2tf32(pa0.x); w.y = f2tf32(pa0.y); w.z = f2tf32(pa0.z); w.w = f2tf32(pa0.w);
        *(uint4*)&As[row * GS + kc] = w;
        w.x = f2tf32(pa1.x); w.y = f2tf32(pa1.y); w.z = f2tf32(pa1.z); w.w = f2tf32(pa1.w);
        *(uint4*)&As[(row + 64) * GS + kc] = w;
        w.x = f2tf32(pb0.x); w.y = f2tf32(pb0.y); w.z = f2tf32(pb0.z); w.w = f2tf32(pb0.w);
        *(uint4*)&Bs[row * GS + kc] = w;
        w.x = f2tf32(pb1.x); w.y = f2tf32(pb1.y); w.z = f2tf32(pb1.z); w.w = f2tf32(pb1.w);
        *(uint4*)&Bs[(row + 64) * GS + kc] = w;
    }
    __syncthreads();

    const int nk = K >> 4;
    for (int ki = 0; ki < nk; ki++) {
        // Prefetch next tile into registers (latency hidden by compute)
        const bool more = (ki + 1 < nk);
        if (more) {
            const float* a2 = Aptr + (ki + 1) * 16;
            const float* b2 = Bptr + (ki + 1) * 16;
            pa0 = *(const float4*)(a2);
            pa1 = *(const float4*)(a2 + rs64);
            pb0 = *(const float4*)(b2);
            pb1 = *(const float4*)(b2 + rs64);
        }

        const uint32_t* Ac = As + (ki & 1) * GEMM_STAGE;
        const uint32_t* Bc = Bs + (ki & 1) * GEMM_STAGE;
#pragma unroll
        for (int kk = 0; kk < 16; kk += 8) {
            uint32_t a[4][4], b[4][2];
#pragma unroll
            for (int i = 0; i < 4; i++) {
                const int r = wm + i * 16 + lr;
                a[i][0] = Ac[r * GS + kk + lc];
                a[i][1] = Ac[(r + 8) * GS + kk + lc];
                a[i][2] = Ac[r * GS + kk + lc + 4];
                a[i][3] = Ac[(r + 8) * GS + kk + lc + 4];
            }
#pragma unroll
            for (int j = 0; j < 4; j++) {
                const int n = wn + j * 8 + lr;
                b[j][0] = Bc[n * GS + kk + lc];
                b[j][1] = Bc[n * GS + kk + lc + 4];
            }
#pragma unroll
            for (int i = 0; i < 4; i++)
#pragma unroll
                for (int j = 0; j < 4; j++)
                    mma8(acc[i][j][0], acc[i][j][1], acc[i][j][2], acc[i][j][3],
                         a[i][0], a[i][1], a[i][2], a[i][3], b[j][0], b[j][1]);
        }

        // Store prefetched tile into the other stage
        if (more) {
            uint32_t* An = As + ((ki + 1) & 1) * GEMM_STAGE;
            uint32_t* Bn = Bs + ((ki + 1) & 1) * GEMM_STAGE;
            uint4 w;
            w.x = f2tf32(pa0.x); w.y = f2tf32(pa0.y); w.z = f2tf32(pa0.z); w.w = f2tf32(pa0.w);
            *(uint4*)&An[row * GS + kc] = w;
            w.x = f2tf32(pa1.x); w.y = f2tf32(pa1.y); w.z = f2tf32(pa1.z); w.w = f2tf32(pa1.w);
            *(uint4*)&An[(row + 64) * GS + kc] = w;
            w.x = f2tf32(pb0.x); w.y = f2tf32(pb0.y); w.z = f2tf32(pb0.z); w.w = f2tf32(pb0.w);
            *(uint4*)&Bn[row * GS + kc] = w;
            w.x = f2tf32(pb1.x); w.y = f2tf32(pb1.y); w.z = f2tf32(pb1.z); w.w = f2tf32(pb1.w);
            *(uint4*)&Bn[(row + 64) * GS + kc] = w;
        }
        __syncthreads();
    }

#pragma unroll
    for (int i = 0; i < 4; i++) {
        const int r = m0 + wm + i * 16 + lr;
#pragma unroll
        for (int j = 0; j < 4; j++) {
            const int c = n0 + wn + j * 8 + 2 * lc;
            const float2 bi = *(const float2*)&bias[c];
            float2 v0 = { acc[i][j][0] + bi.x, acc[i][j][1] + bi.y };
            *(float2*)&C[(size_t)r * N + c] = v0;
            float2 v1 = { acc[i][j][2] + bi.x, acc[i][j][3] + bi.y };
            *(float2*)&C[(size_t)(r + 8) * N + c] = v1;
        }
    }
}

// ---------------------------------------------------------------------------
// Flash attention (tf32 mma) with sink.
// Br=128 q rows per CTA (256 threads, 8 warps x 16 rows), Bc=64.
// Heavy-first scheduling: qt = 15 - blockIdx.x so long CTAs launch first.
// ---------------------------------------------------------------------------
constexpr int AS = 68;
constexpr int VS = 72;
constexpr int ATTN_SMEM =
    (128 * AS + 64 * AS + 64 * VS + 128 * AS) * (int)sizeof(uint32_t); // 105472 B

__global__ __launch_bounds__(256) void attn_tf32(
    const float* __restrict__ qkv,
    const float* __restrict__ sink_logit,
    float* __restrict__ attn_out)
{
    extern __shared__ uint32_t sm[];
    uint32_t* Qs = sm;                   // [128][AS] tf32 (scaled)
    uint32_t* Ks = Qs + 128 * AS;        // [64][AS]
    uint32_t* Vs = Ks + 64 * AS;         // [64][VS]
    uint32_t* Ps = Vs + 64 * VS;         // [128][AS]

    const int qt  = (T / 128 - 1) - blockIdx.x;   // heavy tiles first
    const int h   = blockIdx.y;
    const int b   = blockIdx.z;
    const int tid = threadIdx.x;
    const int lane = tid & 31;
    const int wid  = tid >> 5;
    const int t0   = qt * 128;
    const int mb   = wid * 16;
    const int lr   = lane >> 2;
    const int lc   = lane & 3;
    const float SC = 0.125f;

    // Load Q (scaled, tf32)
    for (int i = tid; i < 128 * 16; i += 256) {
        const int r  = i >> 4;
        const int c4 = (i & 15) << 2;
        float4 v = *(const float4*)&qkv[(size_t)(b * T + t0 + r) * QKV3 + h * D + c4];
        uint4 w = { f2tf32(v.x * SC), f2tf32(v.y * SC), f2tf32(v.z * SC), f2tf32(v.w * SC) };
        *(uint4*)&Qs[r * AS + c4] = w;
    }

    const float sink = sink_logit[h];
    float m0v = sink, m1v = sink, l0 = 1.f, l1 = 1.f;
    float o[8][4] = {};

    const int nkt = 2 * qt + 2;
    float4 pk[4], pv[4];

    // Prologue prefetch kt=0
#pragma unroll
    for (int p = 0; p < 4; p++) {
        const int s  = tid + p * 256;
        const int r  = s >> 4;
        const int c4 = (s & 15) << 2;
        const size_t base = (size_t)(b * T + r) * QKV3 + h * D;
        pk[p] = *(const float4*)&qkv[base + HD + c4];
        pv[p] = *(const float4*)&qkv[base + 2 * HD + c4];
    }

    for (int kt = 0; kt < nkt; kt++) {
        const int kb = kt * 64;
#pragma unroll
        for (int p = 0; p < 4; p++) {
            const int s  = tid + p * 256;
            const int r  = s >> 4;
            const int c4 = (s & 15) << 2;
            uint4 wk = { f2tf32(pk[p].x), f2tf32(pk[p].y), f2tf32(pk[p].z), f2tf32(pk[p].w) };
            *(uint4*)&Ks[r * AS + c4] = wk;
            uint4 wv = { f2tf32(pv[p].x), f2tf32(pv[p].y), f2tf32(pv[p].z), f2tf32(pv[p].w) };
            *(uint4*)&Vs[r * VS + c4] = wv;
        }
        __syncthreads();

        if (kt + 1 < nkt) {
#pragma unroll
            for (int p = 0; p < 4; p++) {
                const int s  = tid + p * 256;
                const int r  = s >> 4;
                const int c4 = (s & 15) << 2;
                const size_t base = (size_t)(b * T + (kt + 1) * 64 + r) * QKV3 + h * D;
                pk[p] = *(const float4*)&qkv[base + HD + c4];
                pv[p] = *(const float4*)&qkv[base + 2 * HD + c4];
            }
        }

        // Warp-level causal skip
        if (kb <= t0 + mb + 15) {
            float s[8][4] = {};
#pragma unroll
            for (int kk = 0; kk < 64; kk += 8) {
                const uint32_t a0 = Qs[(mb + lr) * AS + kk + lc];
                const uint32_t a1 = Qs[(mb + 8 + lr) * AS + kk + lc];
                const uint32_t a2 = Qs[(mb + lr) * AS + kk + lc + 4];
                const uint32_t a3 = Qs[(mb + 8 + lr) * AS + kk + lc + 4];
#pragma unroll
                for (int j = 0; j < 8; j++) {
                    const uint32_t b0 = Ks[(j * 8 + lr) * AS + kk + lc];
                    const uint32_t b1 = Ks[(j * 8 + lr) * AS + kk + lc + 4];
                    mma8(s[j][0], s[j][1], s[j][2], s[j][3], a0, a1, a2, a3, b0, b1);
                }
            }

            if (kb + 63 > t0 + mb) {
                const int qr0 = t0 + mb + lr, qr1 = qr0 + 8;
#pragma unroll
                for (int j = 0; j < 8; j++) {
                    const int c = kb + j * 8 + 2 * lc;
                    if (c     > qr0) s[j][0] = -1e30f;
                    if (c + 1 > qr0) s[j][1] = -1e30f;
                    if (c     > qr1) s[j][2] = -1e30f;
                    if (c + 1 > qr1) s[j][3] = -1e30f;
                }
            }

            float rmax0 = -1e30f, rmax1 = -1e30f;
#pragma unroll
            for (int j = 0; j < 8; j++) {
                rmax0 = fmaxf(rmax0, fmaxf(s[j][0], s[j][1]));
                rmax1 = fmaxf(rmax1, fmaxf(s[j][2], s[j][3]));
            }
            rmax0 = fmaxf(rmax0, __shfl_xor_sync(~0u, rmax0, 1));
            rmax0 = fmaxf(rmax0, __shfl_xor_sync(~0u, rmax0, 2));
            rmax1 = fmaxf(rmax1, __shfl_xor_sync(~0u, rmax1, 1));
            rmax1 = fmaxf(rmax1, __shfl_xor_sync(~0u, rmax1, 2));

            const float mn0 = fmaxf(m0v, rmax0), mn1 = fmaxf(m1v, rmax1);
            const float sc0 = __expf(m0v - mn0), sc1 = __expf(m1v - mn1);
            float rs0 = 0.f, rs1 = 0.f;
#pragma unroll
            for (int j = 0; j < 8; j++) {
                s[j][0] = __expf(s[j][0] - mn0);
                s[j][1] = __expf(s[j][1] - mn0);
                s[j][2] = __expf(s[j][2] - mn1);
                s[j][3] = __expf(s[j][3] - mn1);
                rs0 += s[j][0] + s[j][1];
                rs1 += s[j][2] + s[j][3];
            }
            rs0 += __shfl_xor_sync(~0u, rs0, 1); rs0 += __shfl_xor_sync(~0u, rs0, 2);
            rs1 += __shfl_xor_sync(~0u, rs1, 1); rs1 += __shfl_xor_sync(~0u, rs1, 2);
            l0 = l0 * sc0 + rs0;  l1 = l1 * sc1 + rs1;
            m0v = mn0;  m1v = mn1;

#pragma unroll
            for (int j = 0; j < 8; j++) {
                o[j][0] *= sc0; o[j][1] *= sc0;
                o[j][2] *= sc1; o[j][3] *= sc1;
                const int c = j * 8 + 2 * lc;
                uint2 w0 = { f2tf32(s[j][0]), f2tf32(s[j][1]) };
                *(uint2*)&Ps[(mb + lr) * AS + c] = w0;
                uint2 w1 = { f2tf32(s[j][2]), f2tf32(s[j][3]) };
                *(uint2*)&Ps[(mb + 8 + lr) * AS + c] = w1;
            }
            __syncwarp();

#pragma unroll
            for (int cc = 0; cc < 64; cc += 8) {
                const uint32_t a0 = Ps[(mb + lr) * AS + cc + lc];
                const uint32_t a1 = Ps[(mb + 8 + lr) * AS + cc + lc];
                const uint32_t a2 = Ps[(mb + lr) * AS + cc + lc + 4];
                const uint32_t a3 = Ps[(mb + 8 + lr) * AS + cc + lc + 4];
#pragma unroll
                for (int j = 0; j < 8; j++) {
                    const uint32_t b0 = Vs[(cc + lc) * VS + j * 8 + lr];
                    const uint32_t b1 = Vs[(cc + lc + 4) * VS + j * 8 + lr];
                    mma8(o[j][0], o[j][1], o[j][2], o[j][3], a0, a1, a2, a3, b0, b1);
                }
            }
        }
        __syncthreads();
    }

    const float inv0 = 1.f / l0, inv1 = 1.f / l1;
#pragma unroll
    for (int j = 0; j < 8; j++) {
        const int c = h * D + j * 8 + 2 * lc;
        float2 v0 = { o[j][0] * inv0, o[j][1] * inv0 };
        *(float2*)&attn_out[(size_t)(b * T + t0 + mb + lr) * HD + c] = v0;
        float2 v1 = { o[j][2] * inv1, o[j][3] * inv1 };
        *(float2*)&attn_out[(size_t)(b * T + t0 + mb + 8 + lr) * HD + c] = v1;
    }
}

// ---------------------------------------------------------------------------
// Launch
// ---------------------------------------------------------------------------
extern "C" void kernel_launch(void* const* d_in, const int* in_sizes, int n_in,
                              void* d_out, int out_size)
{
    const float* x      = (const float*)d_in[0];
    const float* W_qkv  = (const float*)d_in[1];
    const float* b_qkv  = (const float*)d_in[2];
    const float* W_proj = (const float*)d_in[3];
    const float* b_proj = (const float*)d_in[4];
    const float* sink   = (const float*)d_in[5];
    float* out = (float*)d_out;

    float* qkvbuf  = nullptr;
    float* attnbuf = nullptr;
    cudaGetSymbolAddress((void**)&qkvbuf, g_qkv);
    cudaGetSymbolAddress((void**)&attnbuf, g_attn);

    cudaFuncSetAttribute(gemm_tf32,
                         cudaFuncAttributeMaxDynamicSharedMemorySize, GEMM_SMEM);
    cudaFuncSetAttribute(attn_tf32,
                         cudaFuncAttributeMaxDynamicSharedMemorySize, ATTN_SMEM);

    // 1) QKV GEMM: (4096,1024) @ (3072,1024)^T -> (4096,3072)
    gemm_tf32<<<dim3(QKV3 / 128, M_ROWS / 128), 256, GEMM_SMEM>>>(
        M_ROWS, QKV3, Cc, x, W_qkv, b_qkv, qkvbuf);

    // 2) Flash attention with sink -> (4096,1024)
    attn_tf32<<<dim3(T / 128, H, Bb), 256, ATTN_SMEM>>>(qkvbuf, sink, attnbuf);

    // 3) Proj GEMM: (4096,1024) @ (1024,1024)^T + bias -> d_out
    gemm_tf32<<<dim3(HD / 128, M_ROWS / 128), 256, GEMM_SMEM>>>(
        M_ROWS, HD, HD, attnbuf, W_proj, b_proj, out);
}

// round 6
// speedup vs baseline: 1.1413x; 1.0463x over previous
#include <cuda_runtime.h>
#include <cstdint>

// Problem constants
constexpr int Bb   = 2;
constexpr int T    = 2048;
constexpr int Cc   = 1024;
constexpr int H    = 16;
constexpr int D    = 64;
constexpr int HD   = H * D;          // 1024
constexpr int QKV3 = 3 * HD;         // 3072
constexpr int M_ROWS = Bb * T;       // 4096

// Scratch (no cudaMalloc allowed)
__device__ float g_qkv[(size_t)M_ROWS * QKV3];   // (B*T, 3072)
__device__ float g_attn[(size_t)M_ROWS * HD];    // (B*T, 1024)

// ---------------------------------------------------------------------------
// tf32 helpers
// ---------------------------------------------------------------------------
__device__ __forceinline__ uint32_t f2tf32(float x) {
    uint32_t r;
    asm("cvt.rna.tf32.f32 %0, %1;" : "=r"(r) : "f"(x));
    return r;
}

// D += A(16x8,row) * B(8x8,col)  tf32 inputs, f32 accum
__device__ __forceinline__ void mma8(float& d0, float& d1, float& d2, float& d3,
                                     uint32_t a0, uint32_t a1, uint32_t a2, uint32_t a3,
                                     uint32_t b0, uint32_t b1) {
    asm volatile(
        "mma.sync.aligned.m16n8k8.row.col.f32.tf32.tf32.f32 "
        "{%0,%1,%2,%3}, {%4,%5,%6,%7}, {%8,%9}, {%0,%1,%2,%3};\n"
        : "+f"(d0), "+f"(d1), "+f"(d2), "+f"(d3)
        : "r"(a0), "r"(a1), "r"(a2), "r"(a3), "r"(b0), "r"(b1));
}

// ---------------------------------------------------------------------------
// tf32 GEMM, double-buffered smem, fat warp tiles.
// C = A @ Bm^T + bias.  A: MxK row-major, Bm: NxK row-major.
// CTA tile 128x128, BK=16, 128 threads = 4 warps, warp tile 64x64.
// Per kk step: 32 LDS.32 feed 32 MMAs (128 B smem traffic per MMA).
// smem stride GS=20 words -> all frag LDS conflict-free.
// ---------------------------------------------------------------------------
constexpr int GS = 20;
constexpr int GEMM_STAGE = 128 * GS;   // words per matrix per stage

__global__ __launch_bounds__(128) void gemm_tf32(
    int M, int N, int K,
    const float* __restrict__ A,
    const float* __restrict__ Bm,
    const float* __restrict__ bias,
    float* __restrict__ C)
{
    __shared__ uint32_t As[2 * GEMM_STAGE];
    __shared__ uint32_t Bs[2 * GEMM_STAGE];

    const int tid  = threadIdx.x;
    const int lane = tid & 31;
    const int wid  = tid >> 5;          // 0..3
    const int wm   = (wid & 1) * 64;    // warp row base
    const int wn   = (wid >> 1) * 64;   // warp col base
    const int m0   = blockIdx.y * 128;
    const int n0   = blockIdx.x * 128;
    const int lr   = lane >> 2;         // 0..7
    const int lc   = lane & 3;          // 0..3

    float acc[4][8][4] = {};

    // Loader mapping: thread covers rows (tid>>2)+p*32, fixed kc=(tid&3)*4
    const int lrow = tid >> 2;           // 0..31
    const int kc   = (tid & 3) << 2;     // 0,4,8,12
    const float* Aptr = &A[(size_t)(m0 + lrow) * K + kc];
    const float* Bptr = &Bm[(size_t)(n0 + lrow) * K + kc];
    const size_t rs32 = (size_t)32 * K;

    float4 pa[4], pb[4];

    // Prologue: load tile 0, store into stage 0
#pragma unroll
    for (int p = 0; p < 4; p++) {
        pa[p] = *(const float4*)(Aptr + p * rs32);
        pb[p] = *(const float4*)(Bptr + p * rs32);
    }
#pragma unroll
    for (int p = 0; p < 4; p++) {
        const int r = lrow + p * 32;
        uint4 wa = { f2tf32(pa[p].x), f2tf32(pa[p].y), f2tf32(pa[p].z), f2tf32(pa[p].w) };
        *(uint4*)&As[r * GS + kc] = wa;
        uint4 wb = { f2tf32(pb[p].x), f2tf32(pb[p].y), f2tf32(pb[p].z), f2tf32(pb[p].w) };
        *(uint4*)&Bs[r * GS + kc] = wb;
    }
    __syncthreads();

    const int nk = K >> 4;
    for (int ki = 0; ki < nk; ki++) {
        const bool more = (ki + 1 < nk);
        if (more) {
            const float* a2 = Aptr + (ki + 1) * 16;
            const float* b2 = Bptr + (ki + 1) * 16;
#pragma unroll
            for (int p = 0; p < 4; p++) {
                pa[p] = *(const float4*)(a2 + p * rs32);
                pb[p] = *(const float4*)(b2 + p * rs32);
            }
        }

        const uint32_t* Ac = As + (ki & 1) * GEMM_STAGE;
        const uint32_t* Bc = Bs + (ki & 1) * GEMM_STAGE;
#pragma unroll
        for (int kk = 0; kk < 16; kk += 8) {
            uint32_t a[4][4], b[8][2];
#pragma unroll
            for (int i = 0; i < 4; i++) {
                const int r = wm + i * 16 + lr;
                a[i][0] = Ac[r * GS + kk + lc];
                a[i][1] = Ac[(r + 8) * GS + kk + lc];
                a[i][2] = Ac[r * GS + kk + lc + 4];
                a[i][3] = Ac[(r + 8) * GS + kk + lc + 4];
            }
#pragma unroll
            for (int j = 0; j < 8; j++) {
                const int n = wn + j * 8 + lr;
                b[j][0] = Bc[n * GS + kk + lc];
                b[j][1] = Bc[n * GS + kk + lc + 4];
            }
#pragma unroll
            for (int i = 0; i < 4; i++)
#pragma unroll
                for (int j = 0; j < 8; j++)
                    mma8(acc[i][j][0], acc[i][j][1], acc[i][j][2], acc[i][j][3],
                         a[i][0], a[i][1], a[i][2], a[i][3], b[j][0], b[j][1]);
        }

        if (more) {
            uint32_t* An = As + ((ki + 1) & 1) * GEMM_STAGE;
            uint32_t* Bn = Bs + ((ki + 1) & 1) * GEMM_STAGE;
#pragma unroll
            for (int p = 0; p < 4; p++) {
                const int r = lrow + p * 32;
                uint4 wa = { f2tf32(pa[p].x), f2tf32(pa[p].y), f2tf32(pa[p].z), f2tf32(pa[p].w) };
                *(uint4*)&An[r * GS + kc] = wa;
                uint4 wb = { f2tf32(pb[p].x), f2tf32(pb[p].y), f2tf32(pb[p].z), f2tf32(pb[p].w) };
                *(uint4*)&Bn[r * GS + kc] = wb;
            }
        }
        __syncthreads();
    }

#pragma unroll
    for (int i = 0; i < 4; i++) {
        const int r = m0 + wm + i * 16 + lr;
#pragma unroll
        for (int j = 0; j < 8; j++) {
            const int c = n0 + wn + j * 8 + 2 * lc;
            const float2 bi = *(const float2*)&bias[c];
            float2 v0 = { acc[i][j][0] + bi.x, acc[i][j][1] + bi.y };
            *(float2*)&C[(size_t)r * N + c] = v0;
            float2 v1 = { acc[i][j][2] + bi.x, acc[i][j][3] + bi.y };
            *(float2*)&C[(size_t)(r + 8) * N + c] = v1;
        }
    }
}

// ---------------------------------------------------------------------------
// Flash attention (tf32 mma) with sink — unchanged from R4 pass.
// Br=128 (256 threads, 8 warps x 16 rows), Bc=64, heavy-first scheduling.
// ---------------------------------------------------------------------------
constexpr int AS = 68;
constexpr int VS = 72;
constexpr int ATTN_SMEM =
    (128 * AS + 64 * AS + 64 * VS + 128 * AS) * (int)sizeof(uint32_t); // 105472 B

__global__ __launch_bounds__(256) void attn_tf32(
    const float* __restrict__ qkv,
    const float* __restrict__ sink_logit,
    float* __restrict__ attn_out)
{
    extern __shared__ uint32_t sm[];
    uint32_t* Qs = sm;
    uint32_t* Ks = Qs + 128 * AS;
    uint32_t* Vs = Ks + 64 * AS;
    uint32_t* Ps = Vs + 64 * VS;

    const int qt  = (T / 128 - 1) - blockIdx.x;   // heavy tiles first
    const int h   = blockIdx.y;
    const int b   = blockIdx.z;
    const int tid = threadIdx.x;
    const int lane = tid & 31;
    const int wid  = tid >> 5;
    const int t0   = qt * 128;
    const int mb   = wid * 16;
    const int lr   = lane >> 2;
    const int lc   = lane & 3;
    const float SC = 0.125f;

    for (int i = tid; i < 128 * 16; i += 256) {
        const int r  = i >> 4;
        const int c4 = (i & 15) << 2;
        float4 v = *(const float4*)&qkv[(size_t)(b * T + t0 + r) * QKV3 + h * D + c4];
        uint4 w = { f2tf32(v.x * SC), f2tf32(v.y * SC), f2tf32(v.z * SC), f2tf32(v.w * SC) };
        *(uint4*)&Qs[r * AS + c4] = w;
    }

    const float sink = sink_logit[h];
    float m0v = sink, m1v = sink, l0 = 1.f, l1 = 1.f;
    float o[8][4] = {};

    const int nkt = 2 * qt + 2;
    float4 pk[4], pv[4];

#pragma unroll
    for (int p = 0; p < 4; p++) {
        const int s  = tid + p * 256;
        const int r  = s >> 4;
        const int c4 = (s & 15) << 2;
        const size_t base = (size_t)(b * T + r) * QKV3 + h * D;
        pk[p] = *(const float4*)&qkv[base + HD + c4];
        pv[p] = *(const float4*)&qkv[base + 2 * HD + c4];
    }

    for (int kt = 0; kt < nkt; kt++) {
        const int kb = kt * 64;
#pragma unroll
        for (int p = 0; p < 4; p++) {
            const int s  = tid + p * 256;
            const int r  = s >> 4;
            const int c4 = (s & 15) << 2;
            uint4 wk = { f2tf32(pk[p].x), f2tf32(pk[p].y), f2tf32(pk[p].z), f2tf32(pk[p].w) };
            *(uint4*)&Ks[r * AS + c4] = wk;
            uint4 wv = { f2tf32(pv[p].x), f2tf32(pv[p].y), f2tf32(pv[p].z), f2tf32(pv[p].w) };
            *(uint4*)&Vs[r * VS + c4] = wv;
        }
        __syncthreads();

        if (kt + 1 < nkt) {
#pragma unroll
            for (int p = 0; p < 4; p++) {
                const int s  = tid + p * 256;
                const int r  = s >> 4;
                const int c4 = (s & 15) << 2;
                const size_t base = (size_t)(b * T + (kt + 1) * 64 + r) * QKV3 + h * D;
                pk[p] = *(const float4*)&qkv[base + HD + c4];
                pv[p] = *(const float4*)&qkv[base + 2 * HD + c4];
            }
        }

        if (kb <= t0 + mb + 15) {
            float s[8][4] = {};
#pragma unroll
            for (int kk = 0; kk < 64; kk += 8) {
                const uint32_t a0 = Qs[(mb + lr) * AS + kk + lc];
                const uint32_t a1 = Qs[(mb + 8 + lr) * AS + kk + lc];
                const uint32_t a2 = Qs[(mb + lr) * AS + kk + lc + 4];
                const uint32_t a3 = Qs[(mb + 8 + lr) * AS + kk + lc + 4];
#pragma unroll
                for (int j = 0; j < 8; j++) {
                    const uint32_t b0 = Ks[(j * 8 + lr) * AS + kk + lc];
                    const uint32_t b1 = Ks[(j * 8 + lr) * AS + kk + lc + 4];
                    mma8(s[j][0], s[j][1], s[j][2], s[j][3], a0, a1, a2, a3, b0, b1);
                }
            }

            if (kb + 63 > t0 + mb) {
                const int qr0 = t0 + mb + lr, qr1 = qr0 + 8;
#pragma unroll
                for (int j = 0; j < 8; j++) {
                    const int c = kb + j * 8 + 2 * lc;
                    if (c     > qr0) s[j][0] = -1e30f;
                    if (c + 1 > qr0) s[j][1] = -1e30f;
                    if (c     > qr1) s[j][2] = -1e30f;
                    if (c + 1 > qr1) s[j][3] = -1e30f;
                }
            }

            float rmax0 = -1e30f, rmax1 = -1e30f;
#pragma unroll
            for (int j = 0; j < 8; j++) {
                rmax0 = fmaxf(rmax0, fmaxf(s[j][0], s[j][1]));
                rmax1 = fmaxf(rmax1, fmaxf(s[j][2], s[j][3]));
            }
            rmax0 = fmaxf(rmax0, __shfl_xor_sync(~0u, rmax0, 1));
            rmax0 = fmaxf(rmax0, __shfl_xor_sync(~0u, rmax0, 2));
            rmax1 = fmaxf(rmax1, __shfl_xor_sync(~0u, rmax1, 1));
            rmax1 = fmaxf(rmax1, __shfl_xor_sync(~0u, rmax1, 2));

            const float mn0 = fmaxf(m0v, rmax0), mn1 = fmaxf(m1v, rmax1);
            const float sc0 = __expf(m0v - mn0), sc1 = __expf(m1v - mn1);
            float rs0 = 0.f, rs1 = 0.f;
#pragma unroll
            for (int j = 0; j < 8; j++) {
                s[j][0] = __expf(s[j][0] - mn0);
                s[j][1] = __expf(s[j][1] - mn0);
                s[j][2] = __expf(s[j][2] - mn1);
                s[j][3] = __expf(s[j][3] - mn1);
                rs0 += s[j][0] + s[j][1];
                rs1 += s[j][2] + s[j][3];
            }
            rs0 += __shfl_xor_sync(~0u, rs0, 1); rs0 += __shfl_xor_sync(~0u, rs0, 2);
            rs1 += __shfl_xor_sync(~0u, rs1, 1); rs1 += __shfl_xor_sync(~0u, rs1, 2);
            l0 = l0 * sc0 + rs0;  l1 = l1 * sc1 + rs1;
            m0v = mn0;  m1v = mn1;

#pragma unroll
            for (int j = 0; j < 8; j++) {
                o[j][0] *= sc0; o[j][1] *= sc0;
                o[j][2] *= sc1; o[j][3] *= sc1;
                const int c = j * 8 + 2 * lc;
                uint2 w0 = { f2tf32(s[j][0]), f2tf32(s[j][1]) };
                *(uint2*)&Ps[(mb + lr) * AS + c] = w0;
                uint2 w1 = { f2tf32(s[j][2]), f2tf32(s[j][3]) };
                *(uint2*)&Ps[(mb + 8 + lr) * AS + c] = w1;
            }
            __syncwarp();

#pragma unroll
            for (int cc = 0; cc < 64; cc += 8) {
                const uint32_t a0 = Ps[(mb + lr) * AS + cc + lc];
                const uint32_t a1 = Ps[(mb + 8 + lr) * AS + cc + lc];
                const uint32_t a2 = Ps[(mb + lr) * AS + cc + lc + 4];
                const uint32_t a3 = Ps[(mb + 8 + lr) * AS + cc + lc + 4];
#pragma unroll
                for (int j = 0; j < 8; j++) {
                    const uint32_t b0 = Vs[(cc + lc) * VS + j * 8 + lr];
                    const uint32_t b1 = Vs[(cc + lc + 4) * VS + j * 8 + lr];
                    mma8(o[j][0], o[j][1], o[j][2], o[j][3], a0, a1, a2, a3, b0, b1);
                }
            }
        }
        __syncthreads();
    }

    const float inv0 = 1.f / l0, inv1 = 1.f / l1;
#pragma unroll
    for (int j = 0; j < 8; j++) {
        const int c = h * D + j * 8 + 2 * lc;
        float2 v0 = { o[j][0] * inv0, o[j][1] * inv0 };
        *(float2*)&attn_out[(size_t)(b * T + t0 + mb + lr) * HD + c] = v0;
        float2 v1 = { o[j][2] * inv1, o[j][3] * inv1 };
        *(float2*)&attn_out[(size_t)(b * T + t0 + mb + 8 + lr) * HD + c] = v1;
    }
}

// ---------------------------------------------------------------------------
// Launch
// ---------------------------------------------------------------------------
extern "C" void kernel_launch(void* const* d_in, const int* in_sizes, int n_in,
                              void* d_out, int out_size)
{
    const float* x      = (const float*)d_in[0];
    const float* W_qkv  = (const float*)d_in[1];
    const float* b_qkv  = (const float*)d_in[2];
    const float* W_proj = (const float*)d_in[3];
    const float* b_proj = (const float*)d_in[4];
    const float* sink   = (const float*)d_in[5];
    float* out = (float*)d_out;

    float* qkvbuf  = nullptr;
    float* attnbuf = nullptr;
    cudaGetSymbolAddress((void**)&qkvbuf, g_qkv);
    cudaGetSymbolAddress((void**)&attnbuf, g_attn);

    cudaFuncSetAttribute(attn_tf32,
                         cudaFuncAttributeMaxDynamicSharedMemorySize, ATTN_SMEM);

    // 1) QKV GEMM: (4096,1024) @ (3072,1024)^T -> (4096,3072)
    gemm_tf32<<<dim3(QKV3 / 128, M_ROWS / 128), 128>>>(
        M_ROWS, QKV3, Cc, x, W_qkv, b_qkv, qkvbuf);

    // 2) Flash attention with sink -> (4096,1024)
    attn_tf32<<<dim3(T / 128, H, Bb), 256, ATTN_SMEM>>>(qkvbuf, sink, attnbuf);

    // 3) Proj GEMM: (4096,1024) @ (1024,1024)^T + bias -> d_out
    gemm_tf32<<<dim3(HD / 128, M_ROWS / 128), 128>>>(
        M_ROWS, HD, HD, attnbuf, W_proj, b_proj, out);
}

// round 7
// speedup vs baseline: 1.4929x; 1.3081x over previous
#include <cuda_runtime.h>
#include <cuda_fp16.h>
#include <cstdint>

// Problem constants
constexpr int Bb   = 2;
constexpr int T    = 2048;
constexpr int Cc   = 1024;
constexpr int H    = 16;
constexpr int D    = 64;
constexpr int HD   = H * D;          // 1024
constexpr int QKV3 = 3 * HD;         // 3072
constexpr int M_ROWS = Bb * T;       // 4096

// Scratch (no cudaMalloc allowed)
__device__ __half g_xh[(size_t)M_ROWS * Cc];
__device__ __half g_wqh[(size_t)QKV3 * Cc];
__device__ __half g_wph[(size_t)HD * HD];
__device__ __half g_qkvh[(size_t)M_ROWS * QKV3];
__device__ __half g_attnh[(size_t)M_ROWS * HD];

// ---------------------------------------------------------------------------
// helpers
// ---------------------------------------------------------------------------
__device__ __forceinline__ uint32_t f2tf32(float x) {
    uint32_t r;
    asm("cvt.rna.tf32.f32 %0, %1;" : "=r"(r) : "f"(x));
    return r;
}
__device__ __forceinline__ uint32_t smem_u32(const void* p) {
    uint32_t a;
    asm("{ .reg .u64 t; cvta.to.shared.u64 t, %1; cvt.u32.u64 %0, t; }"
        : "=r"(a) : "l"(p));
    return a;
}
__device__ __forceinline__ void cp16(uint32_t dst, const void* src) {
    asm volatile("cp.async.cg.shared.global [%0], [%1], 16;"
                 :: "r"(dst), "l"(src) : "memory");
}
#define CP_COMMIT() asm volatile("cp.async.commit_group;" ::: "memory")
#define CP_WAIT2()  asm volatile("cp.async.wait_group 2;"  ::: "memory")

// fp16 m16n8k16, fp32 accumulate
__device__ __forceinline__ void mma16(float& d0, float& d1, float& d2, float& d3,
                                      uint32_t a0, uint32_t a1, uint32_t a2, uint32_t a3,
                                      uint32_t b0, uint32_t b1) {
    asm volatile(
        "mma.sync.aligned.m16n8k16.row.col.f32.f16.f16.f32 "
        "{%0,%1,%2,%3}, {%4,%5,%6,%7}, {%8,%9}, {%0,%1,%2,%3};\n"
        : "+f"(d0), "+f"(d1), "+f"(d2), "+f"(d3)
        : "r"(a0), "r"(a1), "r"(a2), "r"(a3), "r"(b0), "r"(b1));
}
// tf32 m16n8k8 (PV in attention)
__device__ __forceinline__ void mma8(float& d0, float& d1, float& d2, float& d3,
                                     uint32_t a0, uint32_t a1, uint32_t a2, uint32_t a3,
                                     uint32_t b0, uint32_t b1) {
    asm volatile(
        "mma.sync.aligned.m16n8k8.row.col.f32.tf32.tf32.f32 "
        "{%0,%1,%2,%3}, {%4,%5,%6,%7}, {%8,%9}, {%0,%1,%2,%3};\n"
        : "+f"(d0), "+f"(d1), "+f"(d2), "+f"(d3)
        : "r"(a0), "r"(a1), "r"(a2), "r"(a3), "r"(b0), "r"(b1));
}

// ---------------------------------------------------------------------------
// fp32 -> fp16 conversion (grid-stride, vectorized)
// ---------------------------------------------------------------------------
__global__ __launch_bounds__(256) void cvt_f2h(const float* __restrict__ s,
                                               __half* __restrict__ d, int n) {
    int i = (blockIdx.x * blockDim.x + threadIdx.x) * 4;
    const int stride = gridDim.x * blockDim.x * 4;
    for (; i < n; i += stride) {
        float4 v = *(const float4*)(s + i);
        __half2 h0 = __floats2half2_rn(v.x, v.y);
        __half2 h1 = __floats2half2_rn(v.z, v.w);
        uint2 w = { *(uint32_t*)&h0, *(uint32_t*)&h1 };
        *(uint2*)(d + i) = w;
    }
}

// ---------------------------------------------------------------------------
// fp16 GEMM, cp.async 4-stage pipeline: C = A @ Bm^T + bias.
// A: MxK halves row-major, Bm: NxK halves row-major.
// CTA 128x128, BK=32, 128 threads = 4 warps, warp tile 64x64.
// smem: half2 words, row stride GSH=20 (frag LDS conflict-free).
// ---------------------------------------------------------------------------
constexpr int GSH     = 20;
constexpr int STAGE_W = 128 * GSH;                     // words per matrix per stage
constexpr int NSTAGE  = 4;
constexpr int GEMM_SMEM = NSTAGE * 2 * STAGE_W * 4;    // 81920 B

template <bool HALF_OUT>
__global__ __launch_bounds__(128) void gemm_f16(
    int M, int N, int K,
    const __half* __restrict__ A,
    const __half* __restrict__ Bm,
    const float* __restrict__ bias,
    void* __restrict__ Cout)
{
    extern __shared__ __align__(16) uint32_t sh[];
    const uint32_t sbase = smem_u32(sh);

    const int tid  = threadIdx.x;
    const int lane = tid & 31;
    const int wid  = tid >> 5;
    const int wm   = (wid & 1) * 64;
    const int wn   = (wid >> 1) * 64;
    const int m0   = blockIdx.y * 128;
    const int n0   = blockIdx.x * 128;
    const int lr   = lane >> 2;
    const int lc   = lane & 3;

    float acc[4][8][4] = {};

    // one row per thread for each matrix; 4 x 16B cp.async per matrix per stage
    const __half* Arow = A + (size_t)(m0 + tid) * K;
    const __half* Brow = Bm + (size_t)(n0 + tid) * K;
    const int nk = K >> 5;   // BK = 32 halves

    auto issue = [&](int i) {
        const int s = i & (NSTAGE - 1);
        const uint32_t ab = sbase + (uint32_t)(s * 2 * STAGE_W + tid * GSH) * 4;
        const uint32_t bb = ab + STAGE_W * 4;
        const __half* as = Arow + i * 32;
        const __half* bs = Brow + i * 32;
#pragma unroll
        for (int g = 0; g < 4; g++) {
            cp16(ab + g * 16, as + g * 8);
            cp16(bb + g * 16, bs + g * 8);
        }
        CP_COMMIT();
    };

#pragma unroll
    for (int i = 0; i < NSTAGE - 1; i++)
        if (i < nk) issue(i);

    for (int i = 0; i < nk; i++) {
        CP_WAIT2();          // stage i complete (<=2 newer groups pending)
        __syncthreads();     // all threads' stage-i data visible; stage i-1 free

        if (i + NSTAGE - 1 < nk) issue(i + NSTAGE - 1);

        const uint32_t* Ac = sh + (i & (NSTAGE - 1)) * 2 * STAGE_W;
        const uint32_t* Bc = Ac + STAGE_W;
#pragma unroll
        for (int c = 0; c < 2; c++) {   // two k16 chunks per BK=32
            uint32_t a[4][4], b[8][2];
#pragma unroll
            for (int ii = 0; ii < 4; ii++) {
                const int r = wm + ii * 16 + lr;
                a[ii][0] = Ac[r * GSH + c * 8 + lc];
                a[ii][1] = Ac[(r + 8) * GSH + c * 8 + lc];
                a[ii][2] = Ac[r * GSH + c * 8 + lc + 4];
                a[ii][3] = Ac[(r + 8) * GSH + c * 8 + lc + 4];
            }
#pragma unroll
            for (int j = 0; j < 8; j++) {
                const int n = wn + j * 8 + lr;
                b[j][0] = Bc[n * GSH + c * 8 + lc];
                b[j][1] = Bc[n * GSH + c * 8 + lc + 4];
            }
#pragma unroll
            for (int ii = 0; ii < 4; ii++)
#pragma unroll
                for (int j = 0; j < 8; j++)
                    mma16(acc[ii][j][0], acc[ii][j][1], acc[ii][j][2], acc[ii][j][3],
                          a[ii][0], a[ii][1], a[ii][2], a[ii][3], b[j][0], b[j][1]);
        }
    }

#pragma unroll
    for (int ii = 0; ii < 4; ii++) {
        const int r = m0 + wm + ii * 16 + lr;
#pragma unroll
        for (int j = 0; j < 8; j++) {
            const int c = n0 + wn + j * 8 + 2 * lc;
            const float2 bi = *(const float2*)&bias[c];
            const float v00 = acc[ii][j][0] + bi.x, v01 = acc[ii][j][1] + bi.y;
            const float v10 = acc[ii][j][2] + bi.x, v11 = acc[ii][j][3] + bi.y;
            if (HALF_OUT) {
                __half* Ch = (__half*)Cout;
                __half2 h0 = __floats2half2_rn(v00, v01);
                __half2 h1 = __floats2half2_rn(v10, v11);
                *(__half2*)&Ch[(size_t)r * N + c] = h0;
                *(__half2*)&Ch[(size_t)(r + 8) * N + c] = h1;
            } else {
                float* Cf = (float*)Cout;
                float2 f0 = { v00, v01 }, f1 = { v10, v11 };
                *(float2*)&Cf[(size_t)r * N + c] = f0;
                *(float2*)&Cf[(size_t)(r + 8) * N + c] = f1;
            }
        }
    }
}

// ---------------------------------------------------------------------------
// Flash attention with sink. QK^T in fp16 (m16n8k16), PV in tf32 (m16n8k8).
// Br=128 (256 threads, 8 warps x 16 rows), Bc=64, heavy-first scheduling.
// Qs/Ks: half2 words, stride 36. Vs: tf32, stride 72. Ps: tf32, stride 68.
// ---------------------------------------------------------------------------
constexpr int QS = 36;   // words per row (32 data + 4 pad); 4r+lc distinct mod 32
constexpr int VS = 72;
constexpr int PS = 68;
constexpr int ATTN_SMEM =
    (128 * QS + 64 * QS + 64 * VS + 128 * PS) * (int)sizeof(uint32_t); // 80896 B

__global__ __launch_bounds__(256) void attn_f16(
    const __half* __restrict__ qkv,
    const float* __restrict__ sink_logit,
    __half* __restrict__ attn_out)
{
    extern __shared__ __align__(16) uint32_t sm[];
    uint32_t* Qs = sm;                    // [128][QS] half2 words (scaled)
    uint32_t* Ks = Qs + 128 * QS;         // [64][QS]  half2 words
    uint32_t* Vs = Ks + 64 * QS;          // [64][VS]  tf32 words
    uint32_t* Ps = Vs + 64 * VS;          // [128][PS] tf32 words

    const int qt  = (T / 128 - 1) - blockIdx.x;   // heavy tiles first
    const int h   = blockIdx.y;
    const int b   = blockIdx.z;
    const int tid = threadIdx.x;
    const int lane = tid & 31;
    const int wid  = tid >> 5;
    const int t0   = qt * 128;
    const int mb   = wid * 16;
    const int lr   = lane >> 2;
    const int lc   = lane & 3;
    const __half2 SC2 = __float2half2_rn(0.125f);  // exact power of 2

    // Load Q tile (scaled): 128 rows x 8 groups of 8 halves
#pragma unroll
    for (int p = 0; p < 4; p++) {
        const int slot = tid + p * 256;
        const int r = slot >> 3, g = slot & 7;
        uint4 v = *(const uint4*)&qkv[(size_t)(b * T + t0 + r) * QKV3 + h * D + g * 8];
        __half2* hp = (__half2*)&v;
        hp[0] = __hmul2(hp[0], SC2); hp[1] = __hmul2(hp[1], SC2);
        hp[2] = __hmul2(hp[2], SC2); hp[3] = __hmul2(hp[3], SC2);
        *(uint4*)&Qs[r * QS + g * 4] = v;
    }

    const float sink = sink_logit[h];
    float m0v = sink, m1v = sink, l0 = 1.f, l1 = 1.f;
    float o[8][4] = {};

    const int nkt = 2 * qt + 2;
    uint4 pk[2];
    uint2 pv[4];

    // Prologue prefetch kt=0
#pragma unroll
    for (int p = 0; p < 2; p++) {
        const int slot = tid + p * 256;
        const int r = slot >> 3, g = slot & 7;
        pk[p] = *(const uint4*)&qkv[(size_t)(b * T + r) * QKV3 + HD + h * D + g * 8];
    }
#pragma unroll
    for (int p = 0; p < 4; p++) {
        const int slot = tid + p * 256;
        const int r = slot >> 4, q = slot & 15;
        pv[p] = *(const uint2*)&qkv[(size_t)(b * T + r) * QKV3 + 2 * HD + h * D + q * 4];
    }

    for (int kt = 0; kt < nkt; kt++) {
        const int kb = kt * 64;
        // Store K (fp16 passthrough) and V (fp16 -> tf32)
#pragma unroll
        for (int p = 0; p < 2; p++) {
            const int slot = tid + p * 256;
            const int r = slot >> 3, g = slot & 7;
            *(uint4*)&Ks[r * QS + g * 4] = pk[p];
        }
#pragma unroll
        for (int p = 0; p < 4; p++) {
            const int slot = tid + p * 256;
            const int r = slot >> 4, q = slot & 15;
            __half2 h0 = ((__half2*)&pv[p])[0];
            __half2 h1 = ((__half2*)&pv[p])[1];
            float2 f0 = __half22float2(h0), f1 = __half22float2(h1);
            uint4 w = { f2tf32(f0.x), f2tf32(f0.y), f2tf32(f1.x), f2tf32(f1.y) };
            *(uint4*)&Vs[r * VS + q * 4] = w;
        }
        __syncthreads();

        // Prefetch next tile
        if (kt + 1 < nkt) {
#pragma unroll
            for (int p = 0; p < 2; p++) {
                const int slot = tid + p * 256;
                const int r = slot >> 3, g = slot & 7;
                pk[p] = *(const uint4*)&qkv[(size_t)(b * T + kb + 64 + r) * QKV3 + HD + h * D + g * 8];
            }
#pragma unroll
            for (int p = 0; p < 4; p++) {
                const int slot = tid + p * 256;
                const int r = slot >> 4, q = slot & 15;
                pv[p] = *(const uint2*)&qkv[(size_t)(b * T + kb + 64 + r) * QKV3 + 2 * HD + h * D + q * 4];
            }
        }

        if (kb <= t0 + mb + 15) {     // warp-level causal skip
            // S = Q K^T  (fp16, 4 k16 steps)
            float s[8][4] = {};
#pragma unroll
            for (int c = 0; c < 4; c++) {
                const uint32_t a0 = Qs[(mb + lr) * QS + c * 8 + lc];
                const uint32_t a1 = Qs[(mb + 8 + lr) * QS + c * 8 + lc];
                const uint32_t a2 = Qs[(mb + lr) * QS + c * 8 + lc + 4];
                const uint32_t a3 = Qs[(mb + 8 + lr) * QS + c * 8 + lc + 4];
#pragma unroll
                for (int j = 0; j < 8; j++) {
                    const uint32_t b0 = Ks[(j * 8 + lr) * QS + c * 8 + lc];
                    const uint32_t b1 = Ks[(j * 8 + lr) * QS + c * 8 + lc + 4];
                    mma16(s[j][0], s[j][1], s[j][2], s[j][3], a0, a1, a2, a3, b0, b1);
                }
            }

            if (kb + 63 > t0 + mb) {   // diagonal tile: causal mask
                const int qr0 = t0 + mb + lr, qr1 = qr0 + 8;
#pragma unroll
                for (int j = 0; j < 8; j++) {
                    const int c = kb + j * 8 + 2 * lc;
                    if (c     > qr0) s[j][0] = -1e30f;
                    if (c + 1 > qr0) s[j][1] = -1e30f;
                    if (c     > qr1) s[j][2] = -1e30f;
                    if (c + 1 > qr1) s[j][3] = -1e30f;
                }
            }

            // Online softmax
            float rmax0 = -1e30f, rmax1 = -1e30f;
#pragma unroll
            for (int j = 0; j < 8; j++) {
                rmax0 = fmaxf(rmax0, fmaxf(s[j][0], s[j][1]));
                rmax1 = fmaxf(rmax1, fmaxf(s[j][2], s[j][3]));
            }
            rmax0 = fmaxf(rmax0, __shfl_xor_sync(~0u, rmax0, 1));
            rmax0 = fmaxf(rmax0, __shfl_xor_sync(~0u, rmax0, 2));
            rmax1 = fmaxf(rmax1, __shfl_xor_sync(~0u, rmax1, 1));
            rmax1 = fmaxf(rmax1, __shfl_xor_sync(~0u, rmax1, 2));

            const float mn0 = fmaxf(m0v, rmax0), mn1 = fmaxf(m1v, rmax1);
            const float sc0 = __expf(m0v - mn0), sc1 = __expf(m1v - mn1);
            float rs0 = 0.f, rs1 = 0.f;
#pragma unroll
            for (int j = 0; j < 8; j++) {
                s[j][0] = __expf(s[j][0] - mn0);
                s[j][1] = __expf(s[j][1] - mn0);
                s[j][2] = __expf(s[j][2] - mn1);
                s[j][3] = __expf(s[j][3] - mn1);
                rs0 += s[j][0] + s[j][1];
                rs1 += s[j][2] + s[j][3];
            }
            rs0 += __shfl_xor_sync(~0u, rs0, 1); rs0 += __shfl_xor_sync(~0u, rs0, 2);
            rs1 += __shfl_xor_sync(~0u, rs1, 1); rs1 += __shfl_xor_sync(~0u, rs1, 2);
            l0 = l0 * sc0 + rs0;  l1 = l1 * sc1 + rs1;
            m0v = mn0;  m1v = mn1;

#pragma unroll
            for (int j = 0; j < 8; j++) {
                o[j][0] *= sc0; o[j][1] *= sc0;
                o[j][2] *= sc1; o[j][3] *= sc1;
                const int c = j * 8 + 2 * lc;
                uint2 w0 = { f2tf32(s[j][0]), f2tf32(s[j][1]) };
                *(uint2*)&Ps[(mb + lr) * PS + c] = w0;
                uint2 w1 = { f2tf32(s[j][2]), f2tf32(s[j][3]) };
                *(uint2*)&Ps[(mb + 8 + lr) * PS + c] = w1;
            }
            __syncwarp();   // P rows are warp-private

            // O += P @ V (tf32 k8)
#pragma unroll
            for (int cc = 0; cc < 64; cc += 8) {
                const uint32_t a0 = Ps[(mb + lr) * PS + cc + lc];
                const uint32_t a1 = Ps[(mb + 8 + lr) * PS + cc + lc];
                const uint32_t a2 = Ps[(mb + lr) * PS + cc + lc + 4];
                const uint32_t a3 = Ps[(mb + 8 + lr) * PS + cc + lc + 4];
#pragma unroll
                for (int j = 0; j < 8; j++) {
                    const uint32_t b0 = Vs[(cc + lc) * VS + j * 8 + lr];
                    const uint32_t b1 = Vs[(cc + lc + 4) * VS + j * 8 + lr];
                    mma8(o[j][0], o[j][1], o[j][2], o[j][3], a0, a1, a2, a3, b0, b1);
                }
            }
        }
        __syncthreads();
    }

    // Epilogue: write fp16 attention output
    const float inv0 = 1.f / l0, inv1 = 1.f / l1;
#pragma unroll
    for (int j = 0; j < 8; j++) {
        const int c = h * D + j * 8 + 2 * lc;
        __half2 h0 = __floats2half2_rn(o[j][0] * inv0, o[j][1] * inv0);
        *(__half2*)&attn_out[(size_t)(b * T + t0 + mb + lr) * HD + c] = h0;
        __half2 h1 = __floats2half2_rn(o[j][2] * inv1, o[j][3] * inv1);
        *(__half2*)&attn_out[(size_t)(b * T + t0 + mb + 8 + lr) * HD + c] = h1;
    }
}

// ---------------------------------------------------------------------------
// Launch
// ---------------------------------------------------------------------------
extern "C" void kernel_launch(void* const* d_in, const int* in_sizes, int n_in,
                              void* d_out, int out_size)
{
    const float* x      = (const float*)d_in[0];
    const float* W_qkv  = (const float*)d_in[1];
    const float* b_qkv  = (const float*)d_in[2];
    const float* W_proj = (const float*)d_in[3];
    const float* b_proj = (const float*)d_in[4];
    const float* sink   = (const float*)d_in[5];
    float* out = (float*)d_out;

    __half *xh, *wqh, *wph, *qkvh, *attnh;
    cudaGetSymbolAddress((void**)&xh,    g_xh);
    cudaGetSymbolAddress((void**)&wqh,   g_wqh);
    cudaGetSymbolAddress((void**)&wph,   g_wph);
    cudaGetSymbolAddress((void**)&qkvh,  g_qkvh);
    cudaGetSymbolAddress((void**)&attnh, g_attnh);

    cudaFuncSetAttribute(gemm_f16<true>,
                         cudaFuncAttributeMaxDynamicSharedMemorySize, GEMM_SMEM);
    cudaFuncSetAttribute(gemm_f16<false>,
                         cudaFuncAttributeMaxDynamicSharedMemorySize, GEMM_SMEM);
    cudaFuncSetAttribute(attn_f16,
                         cudaFuncAttributeMaxDynamicSharedMemorySize, ATTN_SMEM);

    // 0) fp32 -> fp16 conversions
    cvt_f2h<<<1024, 256>>>(x,      xh,  M_ROWS * Cc);
    cvt_f2h<<<1024, 256>>>(W_qkv,  wqh, QKV3 * Cc);
    cvt_f2h<<<512,  256>>>(W_proj, wph, HD * HD);

    // 1) QKV GEMM (fp16 in/out): (4096,1024) @ (3072,1024)^T -> (4096,3072)
    gemm_f16<true><<<dim3(QKV3 / 128, M_ROWS / 128), 128, GEMM_SMEM>>>(
        M_ROWS, QKV3, Cc, xh, wqh, b_qkv, qkvh);

    // 2) Flash attention with sink -> fp16 (4096,1024)
    attn_f16<<<dim3(T / 128, H, Bb), 256, ATTN_SMEM>>>(qkvh, sink, attnh);

    // 3) Proj GEMM (fp16 in, fp32 out): (4096,1024) @ (1024,1024)^T + bias
    gemm_f16<false><<<dim3(HD / 128, M_ROWS / 128), 128, GEMM_SMEM>>>(
        M_ROWS, HD, HD, attnh, wph, b_proj, out);
}

// round 8
// speedup vs baseline: 1.5596x; 1.0447x over previous
#include <cuda_runtime.h>
#include <cuda_fp16.h>
#include <cstdint>

// Problem constants
constexpr int Bb   = 2;
constexpr int T    = 2048;
constexpr int Cc   = 1024;
constexpr int H    = 16;
constexpr int D    = 64;
constexpr int HD   = H * D;          // 1024
constexpr int QKV3 = 3 * HD;         // 3072
constexpr int M_ROWS = Bb * T;       // 4096

// Scratch (no cudaMalloc allowed)
__device__ __half g_xh[(size_t)M_ROWS * Cc];
__device__ __half g_wqh[(size_t)QKV3 * Cc];
__device__ __half g_wph[(size_t)HD * HD];
__device__ __half g_qkvh[(size_t)M_ROWS * QKV3];
__device__ __half g_attnh[(size_t)M_ROWS * HD];

// ---------------------------------------------------------------------------
// helpers
// ---------------------------------------------------------------------------
__device__ __forceinline__ uint32_t f2tf32(float x) {
    uint32_t r;
    asm("cvt.rna.tf32.f32 %0, %1;" : "=r"(r) : "f"(x));
    return r;
}
__device__ __forceinline__ uint32_t smem_u32(const void* p) {
    uint32_t a;
    asm("{ .reg .u64 t; cvta.to.shared.u64 t, %1; cvt.u32.u64 %0, t; }"
        : "=r"(a) : "l"(p));
    return a;
}
__device__ __forceinline__ void cp16(uint32_t dst, const void* src) {
    asm volatile("cp.async.cg.shared.global [%0], [%1], 16;"
                 :: "r"(dst), "l"(src) : "memory");
}
#define CP_COMMIT() asm volatile("cp.async.commit_group;" ::: "memory")
#define CP_WAIT1()  asm volatile("cp.async.wait_group 1;"  ::: "memory")

__device__ __forceinline__ void ldsm_x4(uint32_t& r0, uint32_t& r1,
                                        uint32_t& r2, uint32_t& r3, uint32_t addr) {
    asm volatile("ldmatrix.sync.aligned.m8n8.x4.shared.b16 {%0,%1,%2,%3}, [%4];"
                 : "=r"(r0), "=r"(r1), "=r"(r2), "=r"(r3) : "r"(addr));
}

// fp16 m16n8k16, fp32 accumulate
__device__ __forceinline__ void mma16(float& d0, float& d1, float& d2, float& d3,
                                      uint32_t a0, uint32_t a1, uint32_t a2, uint32_t a3,
                                      uint32_t b0, uint32_t b1) {
    asm volatile(
        "mma.sync.aligned.m16n8k16.row.col.f32.f16.f16.f32 "
        "{%0,%1,%2,%3}, {%4,%5,%6,%7}, {%8,%9}, {%0,%1,%2,%3};\n"
        : "+f"(d0), "+f"(d1), "+f"(d2), "+f"(d3)
        : "r"(a0), "r"(a1), "r"(a2), "r"(a3), "r"(b0), "r"(b1));
}
// tf32 m16n8k8 (PV in attention)
__device__ __forceinline__ void mma8(float& d0, float& d1, float& d2, float& d3,
                                     uint32_t a0, uint32_t a1, uint32_t a2, uint32_t a3,
                                     uint32_t b0, uint32_t b1) {
    asm volatile(
        "mma.sync.aligned.m16n8k8.row.col.f32.tf32.tf32.f32 "
        "{%0,%1,%2,%3}, {%4,%5,%6,%7}, {%8,%9}, {%0,%1,%2,%3};\n"
        : "+f"(d0), "+f"(d1), "+f"(d2), "+f"(d3)
        : "r"(a0), "r"(a1), "r"(a2), "r"(a3), "r"(b0), "r"(b1));
}

// ---------------------------------------------------------------------------
// fp32 -> fp16 conversion (grid-stride, vectorized)
// ---------------------------------------------------------------------------
__global__ __launch_bounds__(256) void cvt_f2h(const float* __restrict__ s,
                                               __half* __restrict__ d, int n) {
    int i = (blockIdx.x * blockDim.x + threadIdx.x) * 4;
    const int stride = gridDim.x * blockDim.x * 4;
    for (; i < n; i += stride) {
        float4 v = *(const float4*)(s + i);
        __half2 h0 = __floats2half2_rn(v.x, v.y);
        __half2 h1 = __floats2half2_rn(v.z, v.w);
        uint2 w = { *(uint32_t*)&h0, *(uint32_t*)&h1 };
        *(uint2*)(d + i) = w;
    }
}

// ---------------------------------------------------------------------------
// fp16 GEMM, cp.async 3-stage pipeline + ldmatrix: C = A @ Bm^T + bias.
// CTA 128x128, BK=32, 128 threads = 4 warps, warp tile 64x64, 3 CTAs/SM.
// smem: half2 words, row stride GSH=20 (LDSM conflict-free).
// ---------------------------------------------------------------------------
constexpr int GSH     = 20;
constexpr int STAGE_W = 128 * GSH;                     // words per matrix per stage
constexpr int NSTAGE  = 3;
constexpr int GEMM_SMEM = NSTAGE * 2 * STAGE_W * 4;    // 61440 B

template <bool HALF_OUT>
__global__ __launch_bounds__(128, 3) void gemm_f16(
    int M, int N, int K,
    const __half* __restrict__ A,
    const __half* __restrict__ Bm,
    const float* __restrict__ bias,
    void* __restrict__ Cout)
{
    extern __shared__ __align__(16) uint32_t sh[];
    const uint32_t sbase = smem_u32(sh);

    const int tid  = threadIdx.x;
    const int lane = tid & 31;
    const int wid  = tid >> 5;
    const int wm   = (wid & 1) * 64;
    const int wn   = (wid >> 1) * 64;
    const int m0   = blockIdx.y * 128;
    const int n0   = blockIdx.x * 128;
    const int lr   = lane >> 2;
    const int lc   = lane & 3;

    // ldmatrix lane-address components
    const int sub = lane >> 3;         // 0..3 (matrix within x4)
    const int l8  = lane & 7;          // row within 8x8 tile
    // A x4: sub&1 -> +8 rows, sub>>1 -> +8 k-halves (=+4 words)
    const uint32_t aoff = (uint32_t)((((sub & 1) * 8 + l8) * GSH + (sub >> 1) * 4) * 4);
    // B x4: sub>>1 -> +8 n-rows (next n-tile), sub&1 -> +8 k-halves
    const uint32_t boff = (uint32_t)((((sub >> 1) * 8 + l8) * GSH + (sub & 1) * 4) * 4);

    float acc[4][8][4] = {};

    const __half* Arow = A + (size_t)(m0 + tid) * K;
    const __half* Brow = Bm + (size_t)(n0 + tid) * K;
    const int nk = K >> 5;   // BK = 32 halves

    auto issue = [&](int i, int s) {
        const uint32_t ab = sbase + (uint32_t)(s * 2 * STAGE_W + tid * GSH) * 4;
        const uint32_t bb = ab + STAGE_W * 4;
        const __half* as = Arow + i * 32;
        const __half* bs = Brow + i * 32;
#pragma unroll
        for (int g = 0; g < 4; g++) {
            cp16(ab + g * 16, as + g * 8);
            cp16(bb + g * 16, bs + g * 8);
        }
        CP_COMMIT();
    };

    issue(0, 0);
    if (nk > 1) issue(1, 1);

    int s = 0;
    for (int i = 0; i < nk; i++) {
        CP_WAIT1();          // stage i complete
        __syncthreads();

        const int sn = (s + 2 >= NSTAGE) ? s + 2 - NSTAGE : s + 2;
        if (i + 2 < nk) issue(i + 2, sn);

        const uint32_t Ab = sbase + (uint32_t)(s * 2 * STAGE_W) * 4;
        const uint32_t Bb2 = Ab + STAGE_W * 4;
#pragma unroll
        for (int c = 0; c < 2; c++) {   // two k16 chunks per BK=32
            uint32_t a[4][4];
#pragma unroll
            for (int ii = 0; ii < 4; ii++)
                ldsm_x4(a[ii][0], a[ii][1], a[ii][2], a[ii][3],
                        Ab + aoff + (uint32_t)(((wm + ii * 16) * GSH + c * 8) * 4));
#pragma unroll
            for (int jj = 0; jj < 4; jj++) {
                uint32_t b0, b1, b2, b3;
                ldsm_x4(b0, b1, b2, b3,
                        Bb2 + boff + (uint32_t)(((wn + jj * 16) * GSH + c * 8) * 4));
#pragma unroll
                for (int ii = 0; ii < 4; ii++) {
                    mma16(acc[ii][2 * jj][0], acc[ii][2 * jj][1],
                          acc[ii][2 * jj][2], acc[ii][2 * jj][3],
                          a[ii][0], a[ii][1], a[ii][2], a[ii][3], b0, b1);
                    mma16(acc[ii][2 * jj + 1][0], acc[ii][2 * jj + 1][1],
                          acc[ii][2 * jj + 1][2], acc[ii][2 * jj + 1][3],
                          a[ii][0], a[ii][1], a[ii][2], a[ii][3], b2, b3);
                }
            }
        }
        __syncthreads();
        s = (s + 1 >= NSTAGE) ? 0 : s + 1;
    }

#pragma unroll
    for (int ii = 0; ii < 4; ii++) {
        const int r = m0 + wm + ii * 16 + lr;
#pragma unroll
        for (int j = 0; j < 8; j++) {
            const int c = n0 + wn + j * 8 + 2 * lc;
            const float2 bi = *(const float2*)&bias[c];
            const float v00 = acc[ii][j][0] + bi.x, v01 = acc[ii][j][1] + bi.y;
            const float v10 = acc[ii][j][2] + bi.x, v11 = acc[ii][j][3] + bi.y;
            if (HALF_OUT) {
                __half* Ch = (__half*)Cout;
                __half2 h0 = __floats2half2_rn(v00, v01);
                __half2 h1 = __floats2half2_rn(v10, v11);
                *(__half2*)&Ch[(size_t)r * N + c] = h0;
                *(__half2*)&Ch[(size_t)(r + 8) * N + c] = h1;
            } else {
                float* Cf = (float*)Cout;
                float2 f0 = { v00, v01 }, f1 = { v10, v11 };
                *(float2*)&Cf[(size_t)r * N + c] = f0;
                *(float2*)&Cf[(size_t)(r + 8) * N + c] = f1;
            }
        }
    }
}

// ---------------------------------------------------------------------------
// Flash attention with sink. QK^T fp16 (ldmatrix + m16n8k16), PV tf32.
// Br=128 (256 threads, 8 warps x 16 rows), Bc=64, heavy-first scheduling.
// ---------------------------------------------------------------------------
constexpr int QS = 36;   // Q/K row stride in words (half2)
constexpr int VS = 72;   // V row stride in words (tf32)
constexpr int PS = 68;   // P row stride in words (tf32)
constexpr int ATTN_SMEM =
    (128 * QS + 64 * QS + 64 * VS + 128 * PS) * (int)sizeof(uint32_t); // 80896 B

__global__ __launch_bounds__(256) void attn_f16(
    const __half* __restrict__ qkv,
    const float* __restrict__ sink_logit,
    __half* __restrict__ attn_out)
{
    extern __shared__ __align__(16) uint32_t sm[];
    uint32_t* Qs = sm;                    // [128][QS] half2 words (scaled)
    uint32_t* Ks = Qs + 128 * QS;         // [64][QS]  half2 words
    uint32_t* Vs = Ks + 64 * QS;          // [64][VS]  tf32 words
    uint32_t* Ps = Vs + 64 * VS;          // [128][PS] tf32 words
    const uint32_t sbase = smem_u32(sm);
    const uint32_t Kb    = sbase + (uint32_t)(128 * QS) * 4;

    const int qt  = (T / 128 - 1) - blockIdx.x;   // heavy tiles first
    const int h   = blockIdx.y;
    const int b   = blockIdx.z;
    const int tid = threadIdx.x;
    const int lane = tid & 31;
    const int wid  = tid >> 5;
    const int t0   = qt * 128;
    const int mb   = wid * 16;
    const int lr   = lane >> 2;
    const int lc   = lane & 3;
    const int sub  = lane >> 3;
    const int l8   = lane & 7;
    const uint32_t qoff = (uint32_t)((((sub & 1) * 8 + l8) * QS + (sub >> 1) * 4) * 4);
    const uint32_t koff = (uint32_t)((((sub >> 1) * 8 + l8) * QS + (sub & 1) * 4) * 4);
    const __half2 SC2 = __float2half2_rn(0.125f);  // exact power of 2

    // Load Q tile (scaled): 128 rows x 8 groups of 8 halves
#pragma unroll
    for (int p = 0; p < 4; p++) {
        const int slot = tid + p * 256;
        const int r = slot >> 3, g = slot & 7;
        uint4 v = *(const uint4*)&qkv[(size_t)(b * T + t0 + r) * QKV3 + h * D + g * 8];
        __half2* hp = (__half2*)&v;
        hp[0] = __hmul2(hp[0], SC2); hp[1] = __hmul2(hp[1], SC2);
        hp[2] = __hmul2(hp[2], SC2); hp[3] = __hmul2(hp[3], SC2);
        *(uint4*)&Qs[r * QS + g * 4] = v;
    }

    const float sink = sink_logit[h];
    float m0v = sink, m1v = sink, l0 = 1.f, l1 = 1.f;
    float o[8][4] = {};

    const int nkt = 2 * qt + 2;
    uint4 pk[2];
    uint2 pv[4];

    // Prologue prefetch kt=0
#pragma unroll
    for (int p = 0; p < 2; p++) {
        const int slot = tid + p * 256;
        const int r = slot >> 3, g = slot & 7;
        pk[p] = *(const uint4*)&qkv[(size_t)(b * T + r) * QKV3 + HD + h * D + g * 8];
    }
#pragma unroll
    for (int p = 0; p < 4; p++) {
        const int slot = tid + p * 256;
        const int r = slot >> 4, q = slot & 15;
        pv[p] = *(const uint2*)&qkv[(size_t)(b * T + r) * QKV3 + 2 * HD + h * D + q * 4];
    }

    for (int kt = 0; kt < nkt; kt++) {
        const int kb = kt * 64;
        // Store K (fp16 passthrough) and V (fp16 -> tf32)
#pragma unroll
        for (int p = 0; p < 2; p++) {
            const int slot = tid + p * 256;
            const int r = slot >> 3, g = slot & 7;
            *(uint4*)&Ks[r * QS + g * 4] = pk[p];
        }
#pragma unroll
        for (int p = 0; p < 4; p++) {
            const int slot = tid + p * 256;
            const int r = slot >> 4, q = slot & 15;
            __half2 h0 = ((__half2*)&pv[p])[0];
            __half2 h1 = ((__half2*)&pv[p])[1];
            float2 f0 = __half22float2(h0), f1 = __half22float2(h1);
            uint4 w = { f2tf32(f0.x), f2tf32(f0.y), f2tf32(f1.x), f2tf32(f1.y) };
            *(uint4*)&Vs[r * VS + q * 4] = w;
        }
        __syncthreads();

        // Prefetch next tile
        if (kt + 1 < nkt) {
#pragma unroll
            for (int p = 0; p < 2; p++) {
                const int slot = tid + p * 256;
                const int r = slot >> 3, g = slot & 7;
                pk[p] = *(const uint4*)&qkv[(size_t)(b * T + kb + 64 + r) * QKV3 + HD + h * D + g * 8];
            }
#pragma unroll
            for (int p = 0; p < 4; p++) {
                const int slot = tid + p * 256;
                const int r = slot >> 4, q = slot & 15;
                pv[p] = *(const uint2*)&qkv[(size_t)(b * T + kb + 64 + r) * QKV3 + 2 * HD + h * D + q * 4];
            }
        }

        if (kb <= t0 + mb + 15) {     // warp-level causal skip
            // S = Q K^T  (fp16, 4 k16 chunks, ldmatrix frags)
            float s[8][4] = {};
#pragma unroll
            for (int c = 0; c < 4; c++) {
                uint32_t a0, a1, a2, a3;
                ldsm_x4(a0, a1, a2, a3,
                        sbase + qoff + (uint32_t)((mb * QS + c * 8) * 4));
#pragma unroll
                for (int jj = 0; jj < 4; jj++) {
                    uint32_t b0, b1, b2, b3;
                    ldsm_x4(b0, b1, b2, b3,
                            Kb + koff + (uint32_t)((jj * 16 * QS + c * 8) * 4));
                    mma16(s[2 * jj][0], s[2 * jj][1], s[2 * jj][2], s[2 * jj][3],
                          a0, a1, a2, a3, b0, b1);
                    mma16(s[2 * jj + 1][0], s[2 * jj + 1][1], s[2 * jj + 1][2], s[2 * jj + 1][3],
                          a0, a1, a2, a3, b2, b3);
                }
            }

            if (kb + 63 > t0 + mb) {   // diagonal tile: causal mask
                const int qr0 = t0 + mb + lr, qr1 = qr0 + 8;
#pragma unroll
                for (int j = 0; j < 8; j++) {
                    const int c = kb + j * 8 + 2 * lc;
                    if (c     > qr0) s[j][0] = -1e30f;
                    if (c + 1 > qr0) s[j][1] = -1e30f;
                    if (c     > qr1) s[j][2] = -1e30f;
                    if (c + 1 > qr1) s[j][3] = -1e30f;
                }
            }

            // Online softmax
            float rmax0 = -1e30f, rmax1 = -1e30f;
#pragma unroll
            for (int j = 0; j < 8; j++) {
                rmax0 = fmaxf(rmax0, fmaxf(s[j][0], s[j][1]));
                rmax1 = fmaxf(rmax1, fmaxf(s[j][2], s[j][3]));
            }
            rmax0 = fmaxf(rmax0, __shfl_xor_sync(~0u, rmax0, 1));
            rmax0 = fmaxf(rmax0, __shfl_xor_sync(~0u, rmax0, 2));
            rmax1 = fmaxf(rmax1, __shfl_xor_sync(~0u, rmax1, 1));
            rmax1 = fmaxf(rmax1, __shfl_xor_sync(~0u, rmax1, 2));

            const float mn0 = fmaxf(m0v, rmax0), mn1 = fmaxf(m1v, rmax1);
            const float sc0 = __expf(m0v - mn0), sc1 = __expf(m1v - mn1);
            float rs0 = 0.f, rs1 = 0.f;
#pragma unroll
            for (int j = 0; j < 8; j++) {
                s[j][0] = __expf(s[j][0] - mn0);
                s[j][1] = __expf(s[j][1] - mn0);
                s[j][2] = __expf(s[j][2] - mn1);
                s[j][3] = __expf(s[j][3] - mn1);
                rs0 += s[j][0] + s[j][1];
                rs1 += s[j][2] + s[j][3];
            }
            rs0 += __shfl_xor_sync(~0u, rs0, 1); rs0 += __shfl_xor_sync(~0u, rs0, 2);
            rs1 += __shfl_xor_sync(~0u, rs1, 1); rs1 += __shfl_xor_sync(~0u, rs1, 2);
            l0 = l0 * sc0 + rs0;  l1 = l1 * sc1 + rs1;
            m0v = mn0;  m1v = mn1;

#pragma unroll
            for (int j = 0; j < 8; j++) {
                o[j][0] *= sc0; o[j][1] *= sc0;
                o[j][2] *= sc1; o[j][3] *= sc1;
                const int c = j * 8 + 2 * lc;
                uint2 w0 = { f2tf32(s[j][0]), f2tf32(s[j][1]) };
                *(uint2*)&Ps[(mb + lr) * PS + c] = w0;
                uint2 w1 = { f2tf32(s[j][2]), f2tf32(s[j][3]) };
                *(uint2*)&Ps[(mb + 8 + lr) * PS + c] = w1;
            }
            __syncwarp();   // P rows are warp-private

            // O += P @ V (tf32 k8)
#pragma unroll
            for (int cc = 0; cc < 64; cc += 8) {
                const uint32_t a0 = Ps[(mb + lr) * PS + cc + lc];
                const uint32_t a1 = Ps[(mb + 8 + lr) * PS + cc + lc];
                const uint32_t a2 = Ps[(mb + lr) * PS + cc + lc + 4];
                const uint32_t a3 = Ps[(mb + 8 + lr) * PS + cc + lc + 4];
#pragma unroll
                for (int j = 0; j < 8; j++) {
                    const uint32_t b0 = Vs[(cc + lc) * VS + j * 8 + lr];
                    const uint32_t b1 = Vs[(cc + lc + 4) * VS + j * 8 + lr];
                    mma8(o[j][0], o[j][1], o[j][2], o[j][3], a0, a1, a2, a3, b0, b1);
                }
            }
        }
        __syncthreads();
    }

    // Epilogue: write fp16 attention output
    const float inv0 = 1.f / l0, inv1 = 1.f / l1;
#pragma unroll
    for (int j = 0; j < 8; j++) {
        const int c = h * D + j * 8 + 2 * lc;
        __half2 h0 = __floats2half2_rn(o[j][0] * inv0, o[j][1] * inv0);
        *(__half2*)&attn_out[(size_t)(b * T + t0 + mb + lr) * HD + c] = h0;
        __half2 h1 = __floats2half2_rn(o[j][2] * inv1, o[j][3] * inv1);
        *(__half2*)&attn_out[(size_t)(b * T + t0 + mb + 8 + lr) * HD + c] = h1;
    }
}

// ---------------------------------------------------------------------------
// Launch
// ---------------------------------------------------------------------------
extern "C" void kernel_launch(void* const* d_in, const int* in_sizes, int n_in,
                              void* d_out, int out_size)
{
    const float* x      = (const float*)d_in[0];
    const float* W_qkv  = (const float*)d_in[1];
    const float* b_qkv  = (const float*)d_in[2];
    const float* W_proj = (const float*)d_in[3];
    const float* b_proj = (const float*)d_in[4];
    const float* sink   = (const float*)d_in[5];
    float* out = (float*)d_out;

    __half *xh, *wqh, *wph, *qkvh, *attnh;
    cudaGetSymbolAddress((void**)&xh,    g_xh);
    cudaGetSymbolAddress((void**)&wqh,   g_wqh);
    cudaGetSymbolAddress((void**)&wph,   g_wph);
    cudaGetSymbolAddress((void**)&qkvh,  g_qkvh);
    cudaGetSymbolAddress((void**)&attnh, g_attnh);

    cudaFuncSetAttribute(gemm_f16<true>,
                         cudaFuncAttributeMaxDynamicSharedMemorySize, GEMM_SMEM);
    cudaFuncSetAttribute(gemm_f16<false>,
                         cudaFuncAttributeMaxDynamicSharedMemorySize, GEMM_SMEM);
    cudaFuncSetAttribute(attn_f16,
                         cudaFuncAttributeMaxDynamicSharedMemorySize, ATTN_SMEM);

    // 0) fp32 -> fp16 conversions
    cvt_f2h<<<1024, 256>>>(x,      xh,  M_ROWS * Cc);
    cvt_f2h<<<1024, 256>>>(W_qkv,  wqh, QKV3 * Cc);
    cvt_f2h<<<512,  256>>>(W_proj, wph, HD * HD);

    // 1) QKV GEMM (fp16 in/out): (4096,1024) @ (3072,1024)^T -> (4096,3072)
    gemm_f16<true><<<dim3(QKV3 / 128, M_ROWS / 128), 128, GEMM_SMEM>>>(
        M_ROWS, QKV3, Cc, xh, wqh, b_qkv, qkvh);

    // 2) Flash attention with sink -> fp16 (4096,1024)
    attn_f16<<<dim3(T / 128, H, Bb), 256, ATTN_SMEM>>>(qkvh, sink, attnh);

    // 3) Proj GEMM (fp16 in, fp32 out): (4096,1024) @ (1024,1024)^T + bias
    gemm_f16<false><<<dim3(HD / 128, M_ROWS / 128), 128, GEMM_SMEM>>>(
        M_ROWS, HD, HD, attnh, wph, b_proj, out);
}

// round 10
// speedup vs baseline: 1.8486x; 1.1853x over previous
#include <cuda_runtime.h>
#include <cuda_fp16.h>
#include <cstdint>

// Problem constants
constexpr int Bb   = 2;
constexpr int T    = 2048;
constexpr int Cc   = 1024;
constexpr int H    = 16;
constexpr int D    = 64;
constexpr int HD   = H * D;          // 1024
constexpr int QKV3 = 3 * HD;         // 3072
constexpr int M_ROWS = Bb * T;       // 4096

// Scratch (no cudaMalloc allowed)
__device__ __half g_xh[(size_t)M_ROWS * Cc];
__device__ __half g_wqh[(size_t)QKV3 * Cc];
__device__ __half g_wph[(size_t)HD * HD];
__device__ __half g_qkvh[(size_t)M_ROWS * QKV3];
__device__ __half g_attnh[(size_t)M_ROWS * HD];

// ---------------------------------------------------------------------------
// helpers
// ---------------------------------------------------------------------------
__device__ __forceinline__ uint32_t smem_u32(const void* p) {
    uint32_t a;
    asm("{ .reg .u64 t; cvta.to.shared.u64 t, %1; cvt.u32.u64 %0, t; }"
        : "=r"(a) : "l"(p));
    return a;
}
__device__ __forceinline__ void cp16(uint32_t dst, const void* src) {
    asm volatile("cp.async.cg.shared.global [%0], [%1], 16;"
                 :: "r"(dst), "l"(src) : "memory");
}
#define CP_COMMIT() asm volatile("cp.async.commit_group;" ::: "memory")
#define CP_WAIT1()  asm volatile("cp.async.wait_group 1;"  ::: "memory")

__device__ __forceinline__ void ldsm_x4(uint32_t& r0, uint32_t& r1,
                                        uint32_t& r2, uint32_t& r3, uint32_t addr) {
    asm volatile("ldmatrix.sync.aligned.m8n8.x4.shared.b16 {%0,%1,%2,%3}, [%4];"
                 : "=r"(r0), "=r"(r1), "=r"(r2), "=r"(r3) : "r"(addr));
}
__device__ __forceinline__ void ldsm_x4_t(uint32_t& r0, uint32_t& r1,
                                          uint32_t& r2, uint32_t& r3, uint32_t addr) {
    asm volatile("ldmatrix.sync.aligned.m8n8.x4.trans.shared.b16 {%0,%1,%2,%3}, [%4];"
                 : "=r"(r0), "=r"(r1), "=r"(r2), "=r"(r3) : "r"(addr));
}

// fp16 m16n8k16, fp32 accumulate
__device__ __forceinline__ void mma16(float& d0, float& d1, float& d2, float& d3,
                                      uint32_t a0, uint32_t a1, uint32_t a2, uint32_t a3,
                                      uint32_t b0, uint32_t b1) {
    asm volatile(
        "mma.sync.aligned.m16n8k16.row.col.f32.f16.f16.f32 "
        "{%0,%1,%2,%3}, {%4,%5,%6,%7}, {%8,%9}, {%0,%1,%2,%3};\n"
        : "+f"(d0), "+f"(d1), "+f"(d2), "+f"(d3)
        : "r"(a0), "r"(a1), "r"(a2), "r"(a3), "r"(b0), "r"(b1));
}
__device__ __forceinline__ uint32_t packh2(float a, float b) {
    __half2 h = __floats2half2_rn(a, b);
    return *(uint32_t*)&h;
}

// ---------------------------------------------------------------------------
// fp32 -> fp16 conversion (grid-stride, vectorized)
// ---------------------------------------------------------------------------
__global__ __launch_bounds__(256) void cvt_f2h(const float* __restrict__ s,
                                               __half* __restrict__ d, int n) {
    int i = (blockIdx.x * blockDim.x + threadIdx.x) * 4;
    const int stride = gridDim.x * blockDim.x * 4;
    for (; i < n; i += stride) {
        float4 v = *(const float4*)(s + i);
        __half2 h0 = __floats2half2_rn(v.x, v.y);
        __half2 h1 = __floats2half2_rn(v.z, v.w);
        uint2 w = { *(uint32_t*)&h0, *(uint32_t*)&h1 };
        *(uint2*)(d + i) = w;
    }
}

// ---------------------------------------------------------------------------
// fp16 GEMM, cp.async 3-stage pipeline + ldmatrix: C = A @ Bm^T + bias.
// CTA 128x128, BK=32, 128 threads = 4 warps, warp tile 64x64, 3 CTAs/SM.
// One __syncthreads per k-iteration.
// ---------------------------------------------------------------------------
constexpr int GSH     = 20;
constexpr int STAGE_W = 128 * GSH;
constexpr int NSTAGE  = 3;
constexpr int GEMM_SMEM = NSTAGE * 2 * STAGE_W * 4;    // 61440 B

template <bool HALF_OUT>
__global__ __launch_bounds__(128, 3) void gemm_f16(
    int M, int N, int K,
    const __half* __restrict__ A,
    const __half* __restrict__ Bm,
    const float* __restrict__ bias,
    void* __restrict__ Cout)
{
    extern __shared__ __align__(16) uint32_t sh[];
    const uint32_t sbase = smem_u32(sh);

    const int tid  = threadIdx.x;
    const int lane = tid & 31;
    const int wid  = tid >> 5;
    const int wm   = (wid & 1) * 64;
    const int wn   = (wid >> 1) * 64;
    const int m0   = blockIdx.y * 128;
    const int n0   = blockIdx.x * 128;
    const int lr   = lane >> 2;
    const int lc   = lane & 3;
    const int sub  = lane >> 3;
    const int l8   = lane & 7;
    // A-type x4 tiling: sub&1 -> +8 rows, sub>>1 -> +8 k-halves (+4 words)
    const uint32_t aoff = (uint32_t)((((sub & 1) * 8 + l8) * GSH + (sub >> 1) * 4) * 4);
    // B-type x4 tiling: sub>>1 -> +8 n-rows, sub&1 -> +8 k-halves
    const uint32_t boff = (uint32_t)((((sub >> 1) * 8 + l8) * GSH + (sub & 1) * 4) * 4);

    float acc[4][8][4] = {};

    const __half* Arow = A + (size_t)(m0 + tid) * K;
    const __half* Brow = Bm + (size_t)(n0 + tid) * K;
    const int nk = K >> 5;

    auto issue = [&](int i, int s) {
        const uint32_t ab = sbase + (uint32_t)(s * 2 * STAGE_W + tid * GSH) * 4;
        const uint32_t bb = ab + STAGE_W * 4;
        const __half* as = Arow + i * 32;
        const __half* bs = Brow + i * 32;
#pragma unroll
        for (int g = 0; g < 4; g++) {
            cp16(ab + g * 16, as + g * 8);
            cp16(bb + g * 16, bs + g * 8);
        }
        CP_COMMIT();
    };

    issue(0, 0);
    if (nk > 1) issue(1, 1);

    int s = 0;
    for (int i = 0; i < nk; i++) {
        CP_WAIT1();
        __syncthreads();      // orders stage-i visibility AND frees stage (s+2)%3

        const int sn = (s + 2 >= NSTAGE) ? s + 2 - NSTAGE : s + 2;
        if (i + 2 < nk) issue(i + 2, sn);

        const uint32_t Ab = sbase + (uint32_t)(s * 2 * STAGE_W) * 4;
        const uint32_t Bb2 = Ab + STAGE_W * 4;
#pragma unroll
        for (int c = 0; c < 2; c++) {
            uint32_t a[4][4];
#pragma unroll
            for (int ii = 0; ii < 4; ii++)
                ldsm_x4(a[ii][0], a[ii][1], a[ii][2], a[ii][3],
                        Ab + aoff + (uint32_t)(((wm + ii * 16) * GSH + c * 8) * 4));
#pragma unroll
            for (int jj = 0; jj < 4; jj++) {
                uint32_t b0, b1, b2, b3;
                ldsm_x4(b0, b1, b2, b3,
                        Bb2 + boff + (uint32_t)(((wn + jj * 16) * GSH + c * 8) * 4));
#pragma unroll
                for (int ii = 0; ii < 4; ii++) {
                    mma16(acc[ii][2 * jj][0], acc[ii][2 * jj][1],
                          acc[ii][2 * jj][2], acc[ii][2 * jj][3],
                          a[ii][0], a[ii][1], a[ii][2], a[ii][3], b0, b1);
                    mma16(acc[ii][2 * jj + 1][0], acc[ii][2 * jj + 1][1],
                          acc[ii][2 * jj + 1][2], acc[ii][2 * jj + 1][3],
                          a[ii][0], a[ii][1], a[ii][2], a[ii][3], b2, b3);
                }
            }
        }
        s = (s + 1 >= NSTAGE) ? 0 : s + 1;
    }

#pragma unroll
    for (int ii = 0; ii < 4; ii++) {
        const int r = m0 + wm + ii * 16 + lr;
#pragma unroll
        for (int j = 0; j < 8; j++) {
            const int c = n0 + wn + j * 8 + 2 * lc;
            const float2 bi = *(const float2*)&bias[c];
            const float v00 = acc[ii][j][0] + bi.x, v01 = acc[ii][j][1] + bi.y;
            const float v10 = acc[ii][j][2] + bi.x, v11 = acc[ii][j][3] + bi.y;
            if (HALF_OUT) {
                __half* Ch = (__half*)Cout;
                __half2 h0 = __floats2half2_rn(v00, v01);
                __half2 h1 = __floats2half2_rn(v10, v11);
                *(__half2*)&Ch[(size_t)r * N + c] = h0;
                *(__half2*)&Ch[(size_t)(r + 8) * N + c] = h1;
            } else {
                float* Cf = (float*)Cout;
                float2 f0 = { v00, v01 }, f1 = { v10, v11 };
                *(float2*)&Cf[(size_t)r * N + c] = f0;
                *(float2*)&Cf[(size_t)(r + 8) * N + c] = f1;
            }
        }
    }
}

// ---------------------------------------------------------------------------
// Flash attention with sink, all-fp16 MMA (m16n8k16), register-resident P.
// Br=128 (256 threads, 8 warps x 16 rows), Bc=64, heavy-first scheduling.
// Q/K/V smem rows: half2 words, stride 36 (LDSM/LDSM.T conflict-free).
// ---------------------------------------------------------------------------
constexpr int QS = 36;

__global__ __launch_bounds__(256, 2) void attn_f16(
    const __half* __restrict__ qkv,
    const float* __restrict__ sink_logit,
    __half* __restrict__ attn_out)
{
    __shared__ __align__(16) uint32_t sm[(128 + 64 + 64) * QS];  // 36864 B
    uint32_t* Qs = sm;
    uint32_t* Ks = Qs + 128 * QS;
    uint32_t* Vs = Ks + 64 * QS;
    const uint32_t sbase = smem_u32(sm);
    const uint32_t Kb    = sbase + (uint32_t)(128 * QS) * 4;
    const uint32_t Vb    = sbase + (uint32_t)(192 * QS) * 4;

    const int qt  = (T / 128 - 1) - blockIdx.x;   // heavy tiles first
    const int h   = blockIdx.y;
    const int b   = blockIdx.z;
    const int tid = threadIdx.x;
    const int lane = tid & 31;
    const int wid  = tid >> 5;
    const int t0   = qt * 128;
    const int mb   = wid * 16;
    const int lr   = lane >> 2;
    const int lc   = lane & 3;
    const int sub  = lane >> 3;
    const int l8   = lane & 7;
    // A-type tiling for Q (rows = q, k = d)
    const uint32_t qoff = (uint32_t)((((sub & 1) * 8 + l8) * QS + (sub >> 1) * 4) * 4);
    // B-type tiling for K (n-rows = kv, k = d): sub>>1 -> +8 n-rows, sub&1 -> +8 k
    const uint32_t koff = (uint32_t)((((sub >> 1) * 8 + l8) * QS + (sub & 1) * 4) * 4);
    const __half2 SC2 = __float2half2_rn(0.125f);  // exact power of 2

    // Load Q tile (scaled): 128 rows x 8 groups of 8 halves
#pragma unroll
    for (int p = 0; p < 4; p++) {
        const int slot = tid + p * 256;
        const int r = slot >> 3, g = slot & 7;
        uint4 v = *(const uint4*)&qkv[(size_t)(b * T + t0 + r) * QKV3 + h * D + g * 8];
        __half2* hp = (__half2*)&v;
        hp[0] = __hmul2(hp[0], SC2); hp[1] = __hmul2(hp[1], SC2);
        hp[2] = __hmul2(hp[2], SC2); hp[3] = __hmul2(hp[3], SC2);
        *(uint4*)&Qs[r * QS + g * 4] = v;
    }

    const float sink = sink_logit[h];
    float m0v = sink, m1v = sink, l0 = 1.f, l1 = 1.f;
    float o[8][4] = {};

    const int nkt = 2 * qt + 2;
    uint4 pk[2], pv[2];

    // Prologue prefetch kt=0 (64 rows x 8 groups for each of K, V)
#pragma unroll
    for (int p = 0; p < 2; p++) {
        const int slot = tid + p * 256;
        const int r = slot >> 3, g = slot & 7;
        const size_t base = (size_t)(b * T + r) * QKV3 + h * D + g * 8;
        pk[p] = *(const uint4*)&qkv[base + HD];
        pv[p] = *(const uint4*)&qkv[base + 2 * HD];
    }

    for (int kt = 0; kt < nkt; kt++) {
        const int kb = kt * 64;
#pragma unroll
        for (int p = 0; p < 2; p++) {
            const int slot = tid + p * 256;
            const int r = slot >> 3, g = slot & 7;
            *(uint4*)&Ks[r * QS + g * 4] = pk[p];
            *(uint4*)&Vs[r * QS + g * 4] = pv[p];
        }
        __syncthreads();

        if (kt + 1 < nkt) {
#pragma unroll
            for (int p = 0; p < 2; p++) {
                const int slot = tid + p * 256;
                const int r = slot >> 3, g = slot & 7;
                const size_t base = (size_t)(b * T + kb + 64 + r) * QKV3 + h * D + g * 8;
                pk[p] = *(const uint4*)&qkv[base + HD];
                pv[p] = *(const uint4*)&qkv[base + 2 * HD];
            }
        }

        if (kb <= t0 + mb + 15) {     // warp-level causal skip
            // S = Q K^T  (fp16, 4 k16 chunks)
            float s[8][4] = {};
#pragma unroll
            for (int c = 0; c < 4; c++) {
                uint32_t a0, a1, a2, a3;
                ldsm_x4(a0, a1, a2, a3,
                        sbase + qoff + (uint32_t)((mb * QS + c * 8) * 4));
#pragma unroll
                for (int jj = 0; jj < 4; jj++) {
                    uint32_t b0, b1, b2, b3;
                    ldsm_x4(b0, b1, b2, b3,
                            Kb + koff + (uint32_t)((jj * 16 * QS + c * 8) * 4));
                    mma16(s[2 * jj][0], s[2 * jj][1], s[2 * jj][2], s[2 * jj][3],
                          a0, a1, a2, a3, b0, b1);
                    mma16(s[2 * jj + 1][0], s[2 * jj + 1][1], s[2 * jj + 1][2], s[2 * jj + 1][3],
                          a0, a1, a2, a3, b2, b3);
                }
            }

            if (kb + 63 > t0 + mb) {   // diagonal tile: causal mask
                const int qr0 = t0 + mb + lr, qr1 = qr0 + 8;
#pragma unroll
                for (int j = 0; j < 8; j++) {
                    const int c = kb + j * 8 + 2 * lc;
                    if (c     > qr0) s[j][0] = -1e30f;
                    if (c + 1 > qr0) s[j][1] = -1e30f;
                    if (c     > qr1) s[j][2] = -1e30f;
                    if (c + 1 > qr1) s[j][3] = -1e30f;
                }
            }

            // Online softmax
            float rmax0 = -1e30f, rmax1 = -1e30f;
#pragma unroll
            for (int j = 0; j < 8; j++) {
                rmax0 = fmaxf(rmax0, fmaxf(s[j][0], s[j][1]));
                rmax1 = fmaxf(rmax1, fmaxf(s[j][2], s[j][3]));
            }
            rmax0 = fmaxf(rmax0, __shfl_xor_sync(~0u, rmax0, 1));
            rmax0 = fmaxf(rmax0, __shfl_xor_sync(~0u, rmax0, 2));
            rmax1 = fmaxf(rmax1, __shfl_xor_sync(~0u, rmax1, 1));
            rmax1 = fmaxf(rmax1, __shfl_xor_sync(~0u, rmax1, 2));

            const float mn0 = fmaxf(m0v, rmax0), mn1 = fmaxf(m1v, rmax1);
            const float sc0 = __expf(m0v - mn0), sc1 = __expf(m1v - mn1);
            float rs0 = 0.f, rs1 = 0.f;
#pragma unroll
            for (int j = 0; j < 8; j++) {
                s[j][0] = __expf(s[j][0] - mn0);
                s[j][1] = __expf(s[j][1] - mn0);
                s[j][2] = __expf(s[j][2] - mn1);
                s[j][3] = __expf(s[j][3] - mn1);
                rs0 += s[j][0] + s[j][1];
                rs1 += s[j][2] + s[j][3];
            }
            rs0 += __shfl_xor_sync(~0u, rs0, 1); rs0 += __shfl_xor_sync(~0u, rs0, 2);
            rs1 += __shfl_xor_sync(~0u, rs1, 1); rs1 += __shfl_xor_sync(~0u, rs1, 2);
            l0 = l0 * sc0 + rs0;  l1 = l1 * sc1 + rs1;
            m0v = mn0;  m1v = mn1;

            // Pack P into fp16 A-fragments (register-resident, no smem)
            uint32_t pa[4][4];
#pragma unroll
            for (int u = 0; u < 4; u++) {
                pa[u][0] = packh2(s[2 * u][0],     s[2 * u][1]);
                pa[u][1] = packh2(s[2 * u][2],     s[2 * u][3]);
                pa[u][2] = packh2(s[2 * u + 1][0], s[2 * u + 1][1]);
                pa[u][3] = packh2(s[2 * u + 1][2], s[2 * u + 1][3]);
            }

#pragma unroll
            for (int j = 0; j < 8; j++) {
                o[j][0] *= sc0; o[j][1] *= sc0;
                o[j][2] *= sc1; o[j][3] *= sc1;
            }

            // O += P @ V : B-frags via ldmatrix.trans on row-major V
#pragma unroll
            for (int u = 0; u < 4; u++) {       // k chunks (16 kv each)
#pragma unroll
                for (int dd = 0; dd < 4; dd++) { // d chunks (16 cols each)
                    uint32_t b0, b1, b2, b3;
                    ldsm_x4_t(b0, b1, b2, b3,
                        Vb + (uint32_t)(((u * 16 + (sub & 1) * 8 + l8) * QS) * 4
                                        + (dd * 16 + (sub >> 1) * 8) * 2));
                    mma16(o[2 * dd][0], o[2 * dd][1], o[2 * dd][2], o[2 * dd][3],
                          pa[u][0], pa[u][1], pa[u][2], pa[u][3], b0, b1);
                    mma16(o[2 * dd + 1][0], o[2 * dd + 1][1], o[2 * dd + 1][2], o[2 * dd + 1][3],
                          pa[u][0], pa[u][1], pa[u][2], pa[u][3], b2, b3);
                }
            }
        }
        __syncthreads();
    }

    // Epilogue: write fp16 attention output
    const float inv0 = 1.f / l0, inv1 = 1.f / l1;
#pragma unroll
    for (int j = 0; j < 8; j++) {
        const int c = h * D + j * 8 + 2 * lc;
        __half2 h0 = __floats2half2_rn(o[j][0] * inv0, o[j][1] * inv0);
        *(__half2*)&attn_out[(size_t)(b * T + t0 + mb + lr) * HD + c] = h0;
        __half2 h1 = __floats2half2_rn(o[j][2] * inv1, o[j][3] * inv1);
        *(__half2*)&attn_out[(size_t)(b * T + t0 + mb + 8 + lr) * HD + c] = h1;
    }
}

// ---------------------------------------------------------------------------
// Launch
// ---------------------------------------------------------------------------
extern "C" void kernel_launch(void* const* d_in, const int* in_sizes, int n_in,
                              void* d_out, int out_size)
{
    const float* x      = (const float*)d_in[0];
    const float* W_qkv  = (const float*)d_in[1];
    const float* b_qkv  = (const float*)d_in[2];
    const float* W_proj = (const float*)d_in[3];
    const float* b_proj = (const float*)d_in[4];
    const float* sink   = (const float*)d_in[5];
    float* out = (float*)d_out;

    __half *xh, *wqh, *wph, *qkvh, *attnh;
    cudaGetSymbolAddress((void**)&xh,    g_xh);
    cudaGetSymbolAddress((void**)&wqh,   g_wqh);
    cudaGetSymbolAddress((void**)&wph,   g_wph);
    cudaGetSymbolAddress((void**)&qkvh,  g_qkvh);
    cudaGetSymbolAddress((void**)&attnh, g_attnh);

    cudaFuncSetAttribute(gemm_f16<true>,
                         cudaFuncAttributeMaxDynamicSharedMemorySize, GEMM_SMEM);
    cudaFuncSetAttribute(gemm_f16<false>,
                         cudaFuncAttributeMaxDynamicSharedMemorySize, GEMM_SMEM);

    // 0) fp32 -> fp16 conversions
    cvt_f2h<<<1024, 256>>>(x,      xh,  M_ROWS * Cc);
    cvt_f2h<<<1024, 256>>>(W_qkv,  wqh, QKV3 * Cc);
    cvt_f2h<<<512,  256>>>(W_proj, wph, HD * HD);

    // 1) QKV GEMM (fp16 in/out): (4096,1024) @ (3072,1024)^T -> (4096,3072)
    gemm_f16<true><<<dim3(QKV3 / 128, M_ROWS / 128), 128, GEMM_SMEM>>>(
        M_ROWS, QKV3, Cc, xh, wqh, b_qkv, qkvh);

    // 2) Flash attention with sink -> fp16 (4096,1024)
    attn_f16<<<dim3(T / 128, H, Bb), 256>>>(qkvh, sink, attnh);

    // 3) Proj GEMM (fp16 in, fp32 out): (4096,1024) @ (1024,1024)^T + bias
    gemm_f16<false><<<dim3(HD / 128, M_ROWS / 128), 128, GEMM_SMEM>>>(
        M_ROWS, HD, HD, attnh, wph, b_proj, out);
}

// round 11
// speedup vs baseline: 1.9151x; 1.0360x over previous
#include <cuda_runtime.h>
#include <cuda_fp16.h>
#include <cstdint>

// Problem constants
constexpr int Bb   = 2;
constexpr int T    = 2048;
constexpr int Cc   = 1024;
constexpr int H    = 16;
constexpr int D    = 64;
constexpr int HD   = H * D;          // 1024
constexpr int QKV3 = 3 * HD;         // 3072
constexpr int M_ROWS = Bb * T;       // 4096

// Scratch (no cudaMalloc allowed)
__device__ __half g_xh[(size_t)M_ROWS * Cc];
__device__ __half g_wqh[(size_t)QKV3 * Cc];
__device__ __half g_wph[(size_t)HD * HD];
__device__ __half g_qkvh[(size_t)M_ROWS * QKV3];
__device__ __half g_attnh[(size_t)M_ROWS * HD];

// ---------------------------------------------------------------------------
// helpers
// ---------------------------------------------------------------------------
__device__ __forceinline__ uint32_t smem_u32(const void* p) {
    uint32_t a;
    asm("{ .reg .u64 t; cvta.to.shared.u64 t, %1; cvt.u32.u64 %0, t; }"
        : "=r"(a) : "l"(p));
    return a;
}
__device__ __forceinline__ void cp16(uint32_t dst, const void* src) {
    asm volatile("cp.async.cg.shared.global [%0], [%1], 16;"
                 :: "r"(dst), "l"(src) : "memory");
}
#define CP_COMMIT() asm volatile("cp.async.commit_group;" ::: "memory")
#define CP_WAIT1()  asm volatile("cp.async.wait_group 1;"  ::: "memory")
#define CP_WAIT0()  asm volatile("cp.async.wait_group 0;"  ::: "memory")

__device__ __forceinline__ void ldsm_x4(uint32_t& r0, uint32_t& r1,
                                        uint32_t& r2, uint32_t& r3, uint32_t addr) {
    asm volatile("ldmatrix.sync.aligned.m8n8.x4.shared.b16 {%0,%1,%2,%3}, [%4];"
                 : "=r"(r0), "=r"(r1), "=r"(r2), "=r"(r3) : "r"(addr));
}
__device__ __forceinline__ void ldsm_x4_t(uint32_t& r0, uint32_t& r1,
                                          uint32_t& r2, uint32_t& r3, uint32_t addr) {
    asm volatile("ldmatrix.sync.aligned.m8n8.x4.trans.shared.b16 {%0,%1,%2,%3}, [%4];"
                 : "=r"(r0), "=r"(r1), "=r"(r2), "=r"(r3) : "r"(addr));
}

// fp16 m16n8k16, fp32 accumulate
__device__ __forceinline__ void mma16(float& d0, float& d1, float& d2, float& d3,
                                      uint32_t a0, uint32_t a1, uint32_t a2, uint32_t a3,
                                      uint32_t b0, uint32_t b1) {
    asm volatile(
        "mma.sync.aligned.m16n8k16.row.col.f32.f16.f16.f32 "
        "{%0,%1,%2,%3}, {%4,%5,%6,%7}, {%8,%9}, {%0,%1,%2,%3};\n"
        : "+f"(d0), "+f"(d1), "+f"(d2), "+f"(d3)
        : "r"(a0), "r"(a1), "r"(a2), "r"(a3), "r"(b0), "r"(b1));
}
__device__ __forceinline__ uint32_t packh2(float a, float b) {
    __half2 h = __floats2half2_rn(a, b);
    return *(uint32_t*)&h;
}

// ---------------------------------------------------------------------------
// fused fp32 -> fp16 conversion for x, W_qkv, W_proj (grid-stride float4)
// ---------------------------------------------------------------------------
__global__ __launch_bounds__(256) void cvt_all(
    const float* __restrict__ x,  __half* __restrict__ xh,
    const float* __restrict__ wq, __half* __restrict__ wqh,
    const float* __restrict__ wp, __half* __restrict__ wph)
{
    constexpr int n1 = M_ROWS * Cc / 4;
    constexpr int n2 = QKV3 * Cc / 4;
    constexpr int n3 = HD * HD / 4;
    constexpr int total = n1 + n2 + n3;
    int i = blockIdx.x * blockDim.x + threadIdx.x;
    const int stride = gridDim.x * blockDim.x;
    for (; i < total; i += stride) {
        const float* s; __half* d; int j;
        if (i < n1)            { s = x;  d = xh;  j = i; }
        else if (i < n1 + n2)  { s = wq; d = wqh; j = i - n1; }
        else                   { s = wp; d = wph; j = i - n1 - n2; }
        float4 v = *(const float4*)(s + 4 * (size_t)j);
        __half2 h0 = __floats2half2_rn(v.x, v.y);
        __half2 h1 = __floats2half2_rn(v.z, v.w);
        uint2 w = { *(uint32_t*)&h0, *(uint32_t*)&h1 };
        *(uint2*)(d + 4 * (size_t)j) = w;
    }
}

// ---------------------------------------------------------------------------
// fp16 GEMM, cp.async 3-stage pipeline + ldmatrix: C = A @ Bm^T + bias.
// CTA 128x128, BK=32, 128 threads = 4 warps, warp tile 64x64, 3 CTAs/SM.
// (unchanged from R10 — verified at 147 us)
// ---------------------------------------------------------------------------
constexpr int GSH     = 20;
constexpr int STAGE_W = 128 * GSH;
constexpr int NSTAGE  = 3;
constexpr int GEMM_SMEM = NSTAGE * 2 * STAGE_W * 4;    // 61440 B

template <bool HALF_OUT>
__global__ __launch_bounds__(128, 3) void gemm_f16(
    int M, int N, int K,
    const __half* __restrict__ A,
    const __half* __restrict__ Bm,
    const float* __restrict__ bias,
    void* __restrict__ Cout)
{
    extern __shared__ __align__(16) uint32_t sh[];
    const uint32_t sbase = smem_u32(sh);

    const int tid  = threadIdx.x;
    const int lane = tid & 31;
    const int wid  = tid >> 5;
    const int wm   = (wid & 1) * 64;
    const int wn   = (wid >> 1) * 64;
    const int m0   = blockIdx.y * 128;
    const int n0   = blockIdx.x * 128;
    const int lr   = lane >> 2;
    const int lc   = lane & 3;
    const int sub  = lane >> 3;
    const int l8   = lane & 7;
    const uint32_t aoff = (uint32_t)((((sub & 1) * 8 + l8) * GSH + (sub >> 1) * 4) * 4);
    const uint32_t boff = (uint32_t)((((sub >> 1) * 8 + l8) * GSH + (sub & 1) * 4) * 4);

    float acc[4][8][4] = {};

    const __half* Arow = A + (size_t)(m0 + tid) * K;
    const __half* Brow = Bm + (size_t)(n0 + tid) * K;
    const int nk = K >> 5;

    auto issue = [&](int i, int s) {
        const uint32_t ab = sbase + (uint32_t)(s * 2 * STAGE_W + tid * GSH) * 4;
        const uint32_t bb = ab + STAGE_W * 4;
        const __half* as = Arow + i * 32;
        const __half* bs = Brow + i * 32;
#pragma unroll
        for (int g = 0; g < 4; g++) {
            cp16(ab + g * 16, as + g * 8);
            cp16(bb + g * 16, bs + g * 8);
        }
        CP_COMMIT();
    };

    issue(0, 0);
    if (nk > 1) issue(1, 1);

    int s = 0;
    for (int i = 0; i < nk; i++) {
        CP_WAIT1();
        __syncthreads();

        const int sn = (s + 2 >= NSTAGE) ? s + 2 - NSTAGE : s + 2;
        if (i + 2 < nk) issue(i + 2, sn);

        const uint32_t Ab = sbase + (uint32_t)(s * 2 * STAGE_W) * 4;
        const uint32_t Bb2 = Ab + STAGE_W * 4;
#pragma unroll
        for (int c = 0; c < 2; c++) {
            uint32_t a[4][4];
#pragma unroll
            for (int ii = 0; ii < 4; ii++)
                ldsm_x4(a[ii][0], a[ii][1], a[ii][2], a[ii][3],
                        Ab + aoff + (uint32_t)(((wm + ii * 16) * GSH + c * 8) * 4));
#pragma unroll
            for (int jj = 0; jj < 4; jj++) {
                uint32_t b0, b1, b2, b3;
                ldsm_x4(b0, b1, b2, b3,
                        Bb2 + boff + (uint32_t)(((wn + jj * 16) * GSH + c * 8) * 4));
#pragma unroll
                for (int ii = 0; ii < 4; ii++) {
                    mma16(acc[ii][2 * jj][0], acc[ii][2 * jj][1],
                          acc[ii][2 * jj][2], acc[ii][2 * jj][3],
                          a[ii][0], a[ii][1], a[ii][2], a[ii][3], b0, b1);
                    mma16(acc[ii][2 * jj + 1][0], acc[ii][2 * jj + 1][1],
                          acc[ii][2 * jj + 1][2], acc[ii][2 * jj + 1][3],
                          a[ii][0], a[ii][1], a[ii][2], a[ii][3], b2, b3);
                }
            }
        }
        s = (s + 1 >= NSTAGE) ? 0 : s + 1;
    }

#pragma unroll
    for (int ii = 0; ii < 4; ii++) {
        const int r = m0 + wm + ii * 16 + lr;
#pragma unroll
        for (int j = 0; j < 8; j++) {
            const int c = n0 + wn + j * 8 + 2 * lc;
            const float2 bi = *(const float2*)&bias[c];
            const float v00 = acc[ii][j][0] + bi.x, v01 = acc[ii][j][1] + bi.y;
            const float v10 = acc[ii][j][2] + bi.x, v11 = acc[ii][j][3] + bi.y;
            if (HALF_OUT) {
                __half* Ch = (__half*)Cout;
                __half2 h0 = __floats2half2_rn(v00, v01);
                __half2 h1 = __floats2half2_rn(v10, v11);
                *(__half2*)&Ch[(size_t)r * N + c] = h0;
                *(__half2*)&Ch[(size_t)(r + 8) * N + c] = h1;
            } else {
                float* Cf = (float*)Cout;
                float2 f0 = { v00, v01 }, f1 = { v10, v11 };
                *(float2*)&Cf[(size_t)r * N + c] = f0;
                *(float2*)&Cf[(size_t)(r + 8) * N + c] = f1;
            }
        }
    }
}

// ---------------------------------------------------------------------------
// Flash attention with sink, all-fp16 MMA, register-resident P.
// Br=128 (256 threads, 8 warps x 16 rows). K/V pipeline step = 128 kv rows,
// double-buffered via cp.async (one __syncthreads per 128 kv rows).
// Q/K/V smem rows: half2 words, stride 36 (LDSM/LDSM.T conflict-free).
// ---------------------------------------------------------------------------
constexpr int QS = 36;
constexpr int ATTN_STAGE_W = 2 * 128 * QS;                       // K+V words/stage
constexpr int ATTN_SMEM = (128 * QS + 2 * ATTN_STAGE_W) * 4;     // 92160 B

__global__ __launch_bounds__(256, 2) void attn_f16(
    const __half* __restrict__ qkv,
    const float* __restrict__ sink_logit,
    __half* __restrict__ attn_out)
{
    extern __shared__ __align__(16) uint32_t dyn[];
    uint32_t* Qs = dyn;                        // [128][QS]
    const uint32_t sbase = smem_u32(dyn);

    const int qt  = (T / 128 - 1) - blockIdx.x;   // heavy tiles first
    const int h   = blockIdx.y;
    const int b   = blockIdx.z;
    const int tid = threadIdx.x;
    const int lane = tid & 31;
    const int wid  = tid >> 5;
    const int t0   = qt * 128;
    const int mb   = wid * 16;
    const int lr   = lane >> 2;
    const int lc   = lane & 3;
    const int sub  = lane >> 3;
    const int l8   = lane & 7;
    // A-type tiling for Q (rows = q, k = d)
    const uint32_t qoff = (uint32_t)((((sub & 1) * 8 + l8) * QS + (sub >> 1) * 4) * 4);
    // B-type tiling for K (n-rows = kv, k = d)
    const uint32_t koff = (uint32_t)((((sub >> 1) * 8 + l8) * QS + (sub & 1) * 4) * 4);
    const __half2 SC2 = __float2half2_rn(0.125f);  // exact power of 2

    auto kstage = [&](int s) -> uint32_t {
        return sbase + (uint32_t)(128 * QS + s * ATTN_STAGE_W) * 4;
    };
    // cp.async K+V for tile kt (128 kv rows) into stage s
    auto issue_kv = [&](int kt, int s) {
        const uint32_t kb_ = kstage(s);
        const uint32_t vb_ = kb_ + (uint32_t)(128 * QS) * 4;
        const int kv0 = kt * 128;
#pragma unroll
        for (int p = 0; p < 4; p++) {
            const int slot = tid + p * 256;
            const int r = slot >> 3, g = slot & 7;
            const __half* src = qkv + (size_t)(b * T + kv0 + r) * QKV3 + h * D + g * 8;
            const uint32_t doff = (uint32_t)(r * QS + g * 4) * 4;
            cp16(kb_ + doff, src + HD);
            cp16(vb_ + doff, src + 2 * HD);
        }
        CP_COMMIT();
    };

    // Load Q tile (scaled) via plain stores (once)
#pragma unroll
    for (int p = 0; p < 4; p++) {
        const int slot = tid + p * 256;
        const int r = slot >> 3, g = slot & 7;
        uint4 v = *(const uint4*)&qkv[(size_t)(b * T + t0 + r) * QKV3 + h * D + g * 8];
        __half2* hp = (__half2*)&v;
        hp[0] = __hmul2(hp[0], SC2); hp[1] = __hmul2(hp[1], SC2);
        hp[2] = __hmul2(hp[2], SC2); hp[3] = __hmul2(hp[3], SC2);
        *(uint4*)&Qs[r * QS + g * 4] = v;
    }

    const float sink = sink_logit[h];
    float m0v = sink, m1v = sink, l0 = 1.f, l1 = 1.f;
    float o[8][4] = {};

    const int nkt = qt + 1;     // 128-row kv tiles
    issue_kv(0, 0);

    for (int kt = 0; kt < nkt; kt++) {
        CP_WAIT0();             // tile kt data arrived
        __syncthreads();        // visible to all warps; prior compute done
        if (kt + 1 < nkt) issue_kv(kt + 1, (kt + 1) & 1);

        const uint32_t Kb = kstage(kt & 1);
        const uint32_t Vb = Kb + (uint32_t)(128 * QS) * 4;

#pragma unroll
        for (int c2 = 0; c2 < 2; c2++) {      // two 64-kv-row chunks
            const int kb = kt * 128 + c2 * 64;
            if (kb > t0 + mb + 15) continue;  // causal skip (warp-level)
            const uint32_t Kc = Kb + (uint32_t)(c2 * 64 * QS) * 4;
            const uint32_t Vc = Vb + (uint32_t)(c2 * 64 * QS) * 4;

            // S = Q K^T  (fp16, 4 k16 chunks over D)
            float s[8][4] = {};
#pragma unroll
            for (int c = 0; c < 4; c++) {
                uint32_t a0, a1, a2, a3;
                ldsm_x4(a0, a1, a2, a3,
                        sbase + qoff + (uint32_t)((mb * QS + c * 8) * 4));
#pragma unroll
                for (int jj = 0; jj < 4; jj++) {
                    uint32_t b0, b1, b2, b3;
                    ldsm_x4(b0, b1, b2, b3,
                            Kc + koff + (uint32_t)((jj * 16 * QS + c * 8) * 4));
                    mma16(s[2 * jj][0], s[2 * jj][1], s[2 * jj][2], s[2 * jj][3],
                          a0, a1, a2, a3, b0, b1);
                    mma16(s[2 * jj + 1][0], s[2 * jj + 1][1], s[2 * jj + 1][2], s[2 * jj + 1][3],
                          a0, a1, a2, a3, b2, b3);
                }
            }

            if (kb + 63 > t0 + mb) {   // diagonal chunk: causal mask
                const int qr0 = t0 + mb + lr, qr1 = qr0 + 8;
#pragma unroll
                for (int j = 0; j < 8; j++) {
                    const int c = kb + j * 8 + 2 * lc;
                    if (c     > qr0) s[j][0] = -1e30f;
                    if (c + 1 > qr0) s[j][1] = -1e30f;
                    if (c     > qr1) s[j][2] = -1e30f;
                    if (c + 1 > qr1) s[j][3] = -1e30f;
                }
            }

            // Online softmax
            float rmax0 = -1e30f, rmax1 = -1e30f;
#pragma unroll
            for (int j = 0; j < 8; j++) {
                rmax0 = fmaxf(rmax0, fmaxf(s[j][0], s[j][1]));
                rmax1 = fmaxf(rmax1, fmaxf(s[j][2], s[j][3]));
            }
            rmax0 = fmaxf(rmax0, __shfl_xor_sync(~0u, rmax0, 1));
            rmax0 = fmaxf(rmax0, __shfl_xor_sync(~0u, rmax0, 2));
            rmax1 = fmaxf(rmax1, __shfl_xor_sync(~0u, rmax1, 1));
            rmax1 = fmaxf(rmax1, __shfl_xor_sync(~0u, rmax1, 2));

            const float mn0 = fmaxf(m0v, rmax0), mn1 = fmaxf(m1v, rmax1);
            const float sc0 = __expf(m0v - mn0), sc1 = __expf(m1v - mn1);
            float rs0 = 0.f, rs1 = 0.f;
#pragma unroll
            for (int j = 0; j < 8; j++) {
                s[j][0] = __expf(s[j][0] - mn0);
                s[j][1] = __expf(s[j][1] - mn0);
                s[j][2] = __expf(s[j][2] - mn1);
                s[j][3] = __expf(s[j][3] - mn1);
                rs0 += s[j][0] + s[j][1];
                rs1 += s[j][2] + s[j][3];
            }
            rs0 += __shfl_xor_sync(~0u, rs0, 1); rs0 += __shfl_xor_sync(~0u, rs0, 2);
            rs1 += __shfl_xor_sync(~0u, rs1, 1); rs1 += __shfl_xor_sync(~0u, rs1, 2);
            l0 = l0 * sc0 + rs0;  l1 = l1 * sc1 + rs1;
            m0v = mn0;  m1v = mn1;

            // Pack P into fp16 A-fragments (register-resident)
            uint32_t pa[4][4];
#pragma unroll
            for (int u = 0; u < 4; u++) {
                pa[u][0] = packh2(s[2 * u][0],     s[2 * u][1]);
                pa[u][1] = packh2(s[2 * u][2],     s[2 * u][3]);
                pa[u][2] = packh2(s[2 * u + 1][0], s[2 * u + 1][1]);
                pa[u][3] = packh2(s[2 * u + 1][2], s[2 * u + 1][3]);
            }

#pragma unroll
            for (int j = 0; j < 8; j++) {
                o[j][0] *= sc0; o[j][1] *= sc0;
                o[j][2] *= sc1; o[j][3] *= sc1;
            }

            // O += P @ V : B-frags via ldmatrix.trans on row-major V
#pragma unroll
            for (int u = 0; u < 4; u++) {        // kv chunks of 16
#pragma unroll
                for (int dd = 0; dd < 4; dd++) { // d chunks of 16
                    uint32_t b0, b1, b2, b3;
                    ldsm_x4_t(b0, b1, b2, b3,
                        Vc + (uint32_t)(((u * 16 + (sub & 1) * 8 + l8) * QS) * 4
                                        + (dd * 16 + (sub >> 1) * 8) * 2));
                    mma16(o[2 * dd][0], o[2 * dd][1], o[2 * dd][2], o[2 * dd][3],
                          pa[u][0], pa[u][1], pa[u][2], pa[u][3], b0, b1);
                    mma16(o[2 * dd + 1][0], o[2 * dd + 1][1], o[2 * dd + 1][2], o[2 * dd + 1][3],
                          pa[u][0], pa[u][1], pa[u][2], pa[u][3], b2, b3);
                }
            }
        }
    }

    // Epilogue: write fp16 attention output
    const float inv0 = 1.f / l0, inv1 = 1.f / l1;
#pragma unroll
    for (int j = 0; j < 8; j++) {
        const int c = h * D + j * 8 + 2 * lc;
        __half2 h0 = __floats2half2_rn(o[j][0] * inv0, o[j][1] * inv0);
        *(__half2*)&attn_out[(size_t)(b * T + t0 + mb + lr) * HD + c] = h0;
        __half2 h1 = __floats2half2_rn(o[j][2] * inv1, o[j][3] * inv1);
        *(__half2*)&attn_out[(size_t)(b * T + t0 + mb + 8 + lr) * HD + c] = h1;
    }
}

// ---------------------------------------------------------------------------
// Launch
// ---------------------------------------------------------------------------
extern "C" void kernel_launch(void* const* d_in, const int* in_sizes, int n_in,
                              void* d_out, int out_size)
{
    const float* x      = (const float*)d_in[0];
    const float* W_qkv  = (const float*)d_in[1];
    const float* b_qkv  = (const float*)d_in[2];
    const float* W_proj = (const float*)d_in[3];
    const float* b_proj = (const float*)d_in[4];
    const float* sink   = (const float*)d_in[5];
    float* out = (float*)d_out;

    __half *xh, *wqh, *wph, *qkvh, *attnh;
    cudaGetSymbolAddress((void**)&xh,    g_xh);
    cudaGetSymbolAddress((void**)&wqh,   g_wqh);
    cudaGetSymbolAddress((void**)&wph,   g_wph);
    cudaGetSymbolAddress((void**)&qkvh,  g_qkvh);
    cudaGetSymbolAddress((void**)&attnh, g_attnh);

    cudaFuncSetAttribute(gemm_f16<true>,
                         cudaFuncAttributeMaxDynamicSharedMemorySize, GEMM_SMEM);
    cudaFuncSetAttribute(gemm_f16<false>,
                         cudaFuncAttributeMaxDynamicSharedMemorySize, GEMM_SMEM);
    cudaFuncSetAttribute(attn_f16,
                         cudaFuncAttributeMaxDynamicSharedMemorySize, ATTN_SMEM);

    // 0) fused fp32 -> fp16 conversions
    cvt_all<<<2048, 256>>>(x, xh, W_qkv, wqh, W_proj, wph);

    // 1) QKV GEMM (fp16 in/out): (4096,1024) @ (3072,1024)^T -> (4096,3072)
    gemm_f16<true><<<dim3(QKV3 / 128, M_ROWS / 128), 128, GEMM_SMEM>>>(
        M_ROWS, QKV3, Cc, xh, wqh, b_qkv, qkvh);

    // 2) Flash attention with sink -> fp16 (4096,1024)
    attn_f16<<<dim3(T / 128, H, Bb), 256, ATTN_SMEM>>>(qkvh, sink, attnh);

    // 3) Proj GEMM (fp16 in, fp32 out): (4096,1024) @ (1024,1024)^T + bias
    gemm_f16<false><<<dim3(HD / 128, M_ROWS / 128), 128, GEMM_SMEM>>>(
        M_ROWS, HD, HD, attnh, wph, b_proj, out);
}